// round 2
// baseline (speedup 1.0000x reference)
#include <cuda_runtime.h>
#include <math.h>

// Problem constants
#define BB 8
#define LL 1024
#define DD 768
#define HH 12
#define HD 64
#define ROWS (BB*LL)   // 8192

// Scratch (device globals: allocation-free rule)
__device__ float g_tab[HH*4096];          // per-head bias table [12][63*63] (4096 stride)
__device__ float g_xn[ROWS*DD];
__device__ float g_q[ROWS*DD];            // [B,H,L,HD]
__device__ float g_k[ROWS*DD];
__device__ float g_v[ROWS*DD];
__device__ float g_att[ROWS*DD];          // [B,L,D]

// ---------------------------------------------------------------------------
// 1) Per-head bias table over (dy,dx) in [-31,31]^2
// ---------------------------------------------------------------------------
__global__ void bias_tab_kernel(const float* __restrict__ bp)
{
    int h = blockIdx.x;
    float o  = bp[h*6+0];
    float c  = bp[h*6+1];
    float w  = bp[h*6+2];
    float p  = bp[h*6+3];
    float dl = bp[h*6+4];
    float m  = bp[h*6+5];
    float ac = fabsf(c);
    float am = fabsf(m);
    float at = fabsf(tanhf(dl));
    for (int i = threadIdx.x; i < 63*63; i += blockDim.x) {
        int dy = i / 63 - 31;
        int dx = i % 63 - 31;
        float fdy = (float)dy, fdx = (float)dx;
        float theta = atan2f(fdx, fdy);                 // arctan2(dist_x, dist_y)
        float r = sqrtf(fdy*fdy + fdx*fdx + 1e-12f);
        float t1 = powf(fmaxf(r - o, 0.0f), ac);
        float co = cosf((theta - p) * w * 0.5f);
        float t2 = 1.0f - at * powf(co*co, am);
        g_tab[h*4096 + i] = t1 * t2;
    }
}

// ---------------------------------------------------------------------------
// 2) RMSNorm: one block per row
// ---------------------------------------------------------------------------
__global__ __launch_bounds__(256) void rmsnorm_kernel(const float* __restrict__ x,
                                                      const float* __restrict__ wn)
{
    int row = blockIdx.x;
    const float* xr = x + (size_t)row * DD;
    float v[3];
    float s = 0.0f;
#pragma unroll
    for (int t = 0; t < 3; t++) {
        v[t] = xr[threadIdx.x + t*256];
        s += v[t]*v[t];
    }
#pragma unroll
    for (int o = 16; o; o >>= 1) s += __shfl_xor_sync(0xffffffffu, s, o);
    __shared__ float ws[8];
    __shared__ float rfac;
    int lane = threadIdx.x & 31, wid = threadIdx.x >> 5;
    if (lane == 0) ws[wid] = s;
    __syncthreads();
    if (threadIdx.x == 0) {
        float t = 0.0f;
#pragma unroll
        for (int i = 0; i < 8; i++) t += ws[i];
        rfac = rsqrtf(t * (1.0f/768.0f) + 1e-5f);
    }
    __syncthreads();
    float f = rfac;
#pragma unroll
    for (int t = 0; t < 3; t++) {
        int j = threadIdx.x + t*256;
        g_xn[(size_t)row*DD + j] = v[t] * f * wn[j];
    }
}

// ---------------------------------------------------------------------------
// 3/5) NT GEMM: C[M,N] = A[M,K] * Bw[N,K]^T + bias[N]
//      128x128 tile, BK=8, 256 threads, 8x8 micro-tile.
//      SCATTER=true: N=2304, scatter into q/k/v head-major buffers.
// ---------------------------------------------------------------------------
template<bool SCATTER>
__global__ __launch_bounds__(256) void gemm_nt(const float* __restrict__ A,
                                               const float* __restrict__ Bw,
                                               const float* __restrict__ bias,
                                               float* __restrict__ C0,
                                               float* __restrict__ C1,
                                               float* __restrict__ C2,
                                               int N, int Kd)
{
    __shared__ float As[8][128];
    __shared__ float Bs[8][128];

    int tid = threadIdx.x;
    int mBase = blockIdx.y * 128;
    int nBase = blockIdx.x * 128;
    int lr = tid >> 1;           // 0..127
    int lc = (tid & 1) * 4;      // 0 or 4
    const float* Ag = A  + (size_t)(mBase + lr) * Kd + lc;
    const float* Bg = Bw + (size_t)(nBase + lr) * Kd + lc;

    int ty = tid >> 4, tx = tid & 15;
    int r0 = ty * 8, c0 = tx * 8;

    float acc[8][8];
#pragma unroll
    for (int i = 0; i < 8; i++)
#pragma unroll
        for (int j = 0; j < 8; j++) acc[i][j] = 0.0f;

    for (int k0 = 0; k0 < Kd; k0 += 8) {
        float4 av = *(const float4*)(Ag + k0);
        float4 bv = *(const float4*)(Bg + k0);
        __syncthreads();
        As[lc+0][lr] = av.x; As[lc+1][lr] = av.y; As[lc+2][lr] = av.z; As[lc+3][lr] = av.w;
        Bs[lc+0][lr] = bv.x; Bs[lc+1][lr] = bv.y; Bs[lc+2][lr] = bv.z; Bs[lc+3][lr] = bv.w;
        __syncthreads();
#pragma unroll
        for (int kk = 0; kk < 8; kk++) {
            float4 a0 = *(const float4*)&As[kk][r0];
            float4 a1 = *(const float4*)&As[kk][r0+4];
            float4 b0 = *(const float4*)&Bs[kk][c0];
            float4 b1 = *(const float4*)&Bs[kk][c0+4];
            float af[8] = {a0.x,a0.y,a0.z,a0.w,a1.x,a1.y,a1.z,a1.w};
            float bf[8] = {b0.x,b0.y,b0.z,b0.w,b1.x,b1.y,b1.z,b1.w};
#pragma unroll
            for (int i = 0; i < 8; i++)
#pragma unroll
                for (int j = 0; j < 8; j++)
                    acc[i][j] = fmaf(af[i], bf[j], acc[i][j]);
        }
    }

#pragma unroll
    for (int i = 0; i < 8; i++) {
        int gr = mBase + r0 + i;
#pragma unroll
        for (int j = 0; j < 8; j++) {
            int gc = nBase + c0 + j;
            float val = acc[i][j] + bias[gc];
            if (SCATTER) {
                int which = gc / 768;
                int rem = gc - which * 768;
                int h = rem >> 6, hd = rem & 63;
                int b = gr >> 10, l = gr & 1023;
                float* dst = (which == 0) ? C0 : (which == 1 ? C1 : C2);
                dst[(size_t)((b*HH + h)*LL + l)*HD + hd] = val;
            } else {
                C0[(size_t)gr * N + gc] = val;
            }
        }
    }
}

// ---------------------------------------------------------------------------
// 4) Fused flash attention with positional bias table.
//    Grid: (L/128, B*H). 256 threads. Tq=128, Tk=64.
//    Thread (ty,tx): ty in [0,16) owns 8 q-rows, tx in [0,16) owns 4 cols.
// ---------------------------------------------------------------------------
__global__ __launch_bounds__(256) void attn_kernel(float* __restrict__ out)
{
    extern __shared__ float sm[];
    float* Qs  = sm;                    // [128][68]
    float* Ks  = Qs  + 128*68;          // [64][68]
    float* Vs  = Ks  + 64*68;           // [64][68]
    float* Ps  = Vs  + 64*68;           // [128][68]
    float* tabs= Ps  + 128*68;          // [3969]

    int tid = threadIdx.x;
    int qt = blockIdx.x;
    int bh = blockIdx.y;
    int b = bh / HH, h = bh - b * HH;
    int q0 = qt * 128;

    const float* qg  = g_q + ((size_t)bh * LL + q0) * HD;
    const float* kgb = g_k + (size_t)bh * LL * HD;
    const float* vgb = g_v + (size_t)bh * LL * HD;

    for (int i = tid; i < 63*63; i += 256) tabs[i] = g_tab[h*4096 + i];
    for (int i = tid; i < 128*64; i += 256) Qs[(i>>6)*68 + (i&63)] = qg[i];

    int ty = tid >> 4, tx = tid & 15;
    int r0 = ty * 8, c0 = tx * 4;

    float m_i[8], l_i[8], acc_o[8][4];
#pragma unroll
    for (int i = 0; i < 8; i++) {
        m_i[i] = -1e30f; l_i[i] = 0.0f;
#pragma unroll
        for (int j = 0; j < 4; j++) acc_o[i][j] = 0.0f;
    }

    for (int k0 = 0; k0 < LL; k0 += 64) {
        __syncthreads();   // prev P@V done before K/V overwrite (also covers Q/tab on iter 0)
        for (int i = tid; i < 64*64; i += 256) {
            int r = i >> 6, d = i & 63;
            Ks[r*68 + d] = kgb[(size_t)k0*HD + i];
            Vs[r*68 + d] = vgb[(size_t)k0*HD + i];
        }
        __syncthreads();

        // S = Q K^T
        float s[8][4];
#pragma unroll
        for (int i = 0; i < 8; i++)
#pragma unroll
            for (int j = 0; j < 4; j++) s[i][j] = 0.0f;

#pragma unroll 4
        for (int d = 0; d < 64; d++) {
            float af[8], bf[4];
#pragma unroll
            for (int i = 0; i < 8; i++) af[i] = Qs[(r0+i)*68 + d];
#pragma unroll
            for (int j = 0; j < 4; j++) bf[j] = Ks[(c0+j)*68 + d];
#pragma unroll
            for (int i = 0; i < 8; i++)
#pragma unroll
                for (int j = 0; j < 4; j++)
                    s[i][j] = fmaf(af[i], bf[j], s[i][j]);
        }

        // scale + positional bias
#pragma unroll
        for (int i = 0; i < 8; i++) {
            int q = q0 + r0 + i;
            int yq = q >> 5, xq = q & 31;
#pragma unroll
            for (int j = 0; j < 4; j++) {
                int k = k0 + c0 + j;
                int yk = k >> 5, xk = k & 31;
                s[i][j] = s[i][j] * 0.125f + tabs[(yq - yk + 31)*63 + (xq - xk + 31)];
            }
        }

        // online softmax (m/l replicated across the 16 lanes sharing a row)
#pragma unroll
        for (int i = 0; i < 8; i++) {
            float mx = fmaxf(fmaxf(s[i][0], s[i][1]), fmaxf(s[i][2], s[i][3]));
#pragma unroll
            for (int o = 8; o; o >>= 1) mx = fmaxf(mx, __shfl_xor_sync(0xffffffffu, mx, o));
            float mn = fmaxf(m_i[i], mx);
            float sc = __expf(m_i[i] - mn);
            float rs = 0.0f;
#pragma unroll
            for (int j = 0; j < 4; j++) {
                float pv = __expf(s[i][j] - mn);
                s[i][j] = pv;
                rs += pv;
            }
#pragma unroll
            for (int o = 8; o; o >>= 1) rs += __shfl_xor_sync(0xffffffffu, rs, o);
            l_i[i] = l_i[i] * sc + rs;
            m_i[i] = mn;
#pragma unroll
            for (int j = 0; j < 4; j++) acc_o[i][j] *= sc;
#pragma unroll
            for (int j = 0; j < 4; j++) Ps[(r0+i)*68 + c0 + j] = s[i][j];
        }
        __syncthreads();

        // O += P V
#pragma unroll 2
        for (int kk = 0; kk < 64; kk++) {
            float pf[8], vf[4];
#pragma unroll
            for (int i = 0; i < 8; i++) pf[i] = Ps[(r0+i)*68 + kk];
#pragma unroll
            for (int j = 0; j < 4; j++) vf[j] = Vs[kk*68 + c0 + j];
#pragma unroll
            for (int i = 0; i < 8; i++)
#pragma unroll
                for (int j = 0; j < 4; j++)
                    acc_o[i][j] = fmaf(pf[i], vf[j], acc_o[i][j]);
        }
    }

    // normalize + write [B,L,D]
#pragma unroll
    for (int i = 0; i < 8; i++) {
        float inv = 1.0f / l_i[i];
        int l = q0 + r0 + i;
#pragma unroll
        for (int j = 0; j < 4; j++)
            out[(size_t)(b*LL + l)*DD + h*HD + c0 + j] = acc_o[i][j] * inv;
    }
}

// ---------------------------------------------------------------------------
extern "C" void kernel_launch(void* const* d_in, const int* in_sizes, int n_in,
                              void* d_out, int out_size)
{
    const float* x     = (const float*)d_in[0];
    // d_in[1] = pos (32x32 grid, identical per batch — folded into table indexing)
    const float* wn    = (const float*)d_in[2];
    const float* w_in  = (const float*)d_in[3];
    const float* b_in  = (const float*)d_in[4];
    const float* w_out = (const float*)d_in[5];
    const float* b_out = (const float*)d_in[6];
    const float* bp    = (const float*)d_in[7];
    float* out = (float*)d_out;

    float *p_xn, *p_q, *p_k, *p_v, *p_att;
    cudaGetSymbolAddress((void**)&p_xn,  g_xn);
    cudaGetSymbolAddress((void**)&p_q,   g_q);
    cudaGetSymbolAddress((void**)&p_k,   g_k);
    cudaGetSymbolAddress((void**)&p_v,   g_v);
    cudaGetSymbolAddress((void**)&p_att, g_att);

    bias_tab_kernel<<<HH, 256>>>(bp);
    rmsnorm_kernel<<<ROWS, 256>>>(x, wn);
    gemm_nt<true><<<dim3(2304/128, ROWS/128), 256>>>(p_xn, w_in, b_in, p_q, p_k, p_v, 2304, DD);

    size_t smem = (size_t)(128*68 + 64*68 + 64*68 + 128*68 + 63*63) * sizeof(float);
    cudaFuncSetAttribute(attn_kernel, cudaFuncAttributeMaxDynamicSharedMemorySize, (int)smem);
    attn_kernel<<<dim3(LL/128, BB*HH), 256, smem>>>(p_att);

    gemm_nt<false><<<dim3(DD/128, ROWS/128), 256>>>(p_att, w_out, b_out, out, nullptr, nullptr, DD, DD);
}

// round 4
// speedup vs baseline: 1.5662x; 1.5662x over previous
#include <cuda_runtime.h>
#include <math.h>
#include <stdint.h>

// Problem constants
#define BB 8
#define LL 1024
#define DD 768
#define HH 12
#define HD 64
#define ROWS (BB*LL)   // 8192

// Scratch (device globals: allocation-free rule)
__device__ float g_tab[HH*4096];          // per-head bias table [12][63*63]
__device__ float g_xn[ROWS*DD];           // tf32-rounded RMSNorm output
__device__ float g_win[3*DD*DD];          // tf32-rounded w_in
__device__ float g_wout[DD*DD];           // tf32-rounded w_out
__device__ float g_q[ROWS*DD];            // [B,H,L,HD]
__device__ float g_k[ROWS*DD];
__device__ float g_v[ROWS*DD];
__device__ float g_att[ROWS*DD];          // [B,L,D], tf32-rounded

// ---------------------------------------------------------------------------
// helpers
// ---------------------------------------------------------------------------
__device__ __forceinline__ float to_tf32(float x) {
    uint32_t y;
    asm("cvt.rna.tf32.f32 %0, %1;" : "=r"(y) : "f"(x));
    return __uint_as_float(y);
}
__device__ __forceinline__ uint32_t smem_u32(const void* p) {
    uint32_t a;
    asm("{ .reg .u64 t; cvta.to.shared.u64 t, %1; cvt.u32.u64 %0, t; }" : "=r"(a) : "l"(p));
    return a;
}
__device__ __forceinline__ void cpasync16(uint32_t saddr, const void* g) {
    asm volatile("cp.async.cg.shared.global [%0], [%1], 16;" :: "r"(saddr), "l"(g));
}
__device__ __forceinline__ void cp_commit() {
    asm volatile("cp.async.commit_group;" ::: "memory");
}
template<int NN>
__device__ __forceinline__ void cp_wait() {
    asm volatile("cp.async.wait_group %0;" :: "n"(NN) : "memory");
}
__device__ __forceinline__ void mma_tf32(float* d, const uint32_t* a, const uint32_t* b) {
    asm volatile(
        "mma.sync.aligned.m16n8k8.row.col.f32.tf32.tf32.f32 "
        "{%0,%1,%2,%3}, {%4,%5,%6,%7}, {%8,%9}, {%0,%1,%2,%3};"
        : "+f"(d[0]), "+f"(d[1]), "+f"(d[2]), "+f"(d[3])
        : "r"(a[0]), "r"(a[1]), "r"(a[2]), "r"(a[3]), "r"(b[0]), "r"(b[1]));
}

// ---------------------------------------------------------------------------
// 0) tf32-round a weight matrix
// ---------------------------------------------------------------------------
__global__ void cvt_tf32_kernel(const float* __restrict__ src, float* __restrict__ dst, int n)
{
    int i = blockIdx.x * 256 + threadIdx.x;
    if (i < n) dst[i] = to_tf32(src[i]);
}

// ---------------------------------------------------------------------------
// 1) Per-head bias table over (dy,dx) in [-31,31]^2
// ---------------------------------------------------------------------------
__global__ void bias_tab_kernel(const float* __restrict__ bp)
{
    int h = blockIdx.x;
    float o  = bp[h*6+0];
    float c  = bp[h*6+1];
    float w  = bp[h*6+2];
    float p  = bp[h*6+3];
    float dl = bp[h*6+4];
    float m  = bp[h*6+5];
    float ac = fabsf(c);
    float am = fabsf(m);
    float at = fabsf(tanhf(dl));
    for (int i = threadIdx.x; i < 63*63; i += blockDim.x) {
        int dy = i / 63 - 31;
        int dx = i % 63 - 31;
        float fdy = (float)dy, fdx = (float)dx;
        float theta = atan2f(fdx, fdy);
        float r = sqrtf(fdy*fdy + fdx*fdx + 1e-12f);
        float t1 = powf(fmaxf(r - o, 0.0f), ac);
        float co = cosf((theta - p) * w * 0.5f);
        float t2 = 1.0f - at * powf(co*co, am);
        g_tab[h*4096 + i] = t1 * t2;
    }
}

// ---------------------------------------------------------------------------
// 2) RMSNorm: one block per row; output tf32-rounded (A operand of GEMM1)
// ---------------------------------------------------------------------------
__global__ __launch_bounds__(256) void rmsnorm_kernel(const float* __restrict__ x,
                                                      const float* __restrict__ wn)
{
    int row = blockIdx.x;
    const float* xr = x + (size_t)row * DD;
    float v[3];
    float s = 0.0f;
#pragma unroll
    for (int t = 0; t < 3; t++) {
        v[t] = xr[threadIdx.x + t*256];
        s += v[t]*v[t];
    }
#pragma unroll
    for (int o = 16; o; o >>= 1) s += __shfl_xor_sync(0xffffffffu, s, o);
    __shared__ float ws[8];
    __shared__ float rfac;
    int lane = threadIdx.x & 31, wid = threadIdx.x >> 5;
    if (lane == 0) ws[wid] = s;
    __syncthreads();
    if (threadIdx.x == 0) {
        float t = 0.0f;
#pragma unroll
        for (int i = 0; i < 8; i++) t += ws[i];
        rfac = rsqrtf(t * (1.0f/768.0f) + 1e-5f);
    }
    __syncthreads();
    float f = rfac;
#pragma unroll
    for (int t = 0; t < 3; t++) {
        int j = threadIdx.x + t*256;
        g_xn[(size_t)row*DD + j] = to_tf32(v[t] * f * wn[j]);
    }
}

// ---------------------------------------------------------------------------
// 3/5) tf32 mma.sync NT GEMM: C[M,N] = A[M,768] * Bw[N,768]^T + bias[N]
//      CTA 128x128, BK=32 double-buffered cp.async, 8 warps (2x4), warp 64x32.
//      SCATTER=true: scatter into q/k/v head-major buffers.
// ---------------------------------------------------------------------------
#define SP 40   // smem row stride (floats); 160B = 16B-aligned rows

template<bool SCATTER>
__global__ __launch_bounds__(256) void gemm_mma(const float* __restrict__ A,
                                                const float* __restrict__ Bw,
                                                const float* __restrict__ bias,
                                                float* __restrict__ C0,
                                                float* __restrict__ C1,
                                                float* __restrict__ C2,
                                                int N)
{
    extern __shared__ float sm[];
    float* As = sm;                 // [2][128][SP]
    float* Bs = sm + 2*128*SP;      // [2][128][SP]
    uint32_t sA = smem_u32(As), sB = smem_u32(Bs);

    int tid = threadIdx.x;
    int wid = tid >> 5, lane = tid & 31;
    int warp_m = wid >> 2, warp_n = wid & 3;       // 2 x 4
    int g = lane >> 2, c = lane & 3;

    int mBase = blockIdx.y * 128, nBase = blockIdx.x * 128;

    // per-thread staging coords: 4 float4 each for A and B per BK tile
    int srow[4], sc4[4];
#pragma unroll
    for (int t = 0; t < 4; t++) {
        int i = tid + t*256;         // 0..1023
        srow[t] = i >> 3;            // 0..127
        sc4[t]  = i & 7;             // 0..7
    }
    const float* Agp = A  + (size_t)mBase * DD;
    const float* Bgp = Bw + (size_t)nBase * DD;

    float acc[4][4][4];
#pragma unroll
    for (int mt = 0; mt < 4; mt++)
#pragma unroll
        for (int nt = 0; nt < 4; nt++)
#pragma unroll
            for (int r = 0; r < 4; r++) acc[mt][nt][r] = 0.0f;

    const int NT = DD / 32;   // 24 BK-tiles

    // prologue: issue stage 0
#pragma unroll
    for (int t = 0; t < 4; t++) {
        cpasync16(sA + (uint32_t)(srow[t]*SP + sc4[t]*4)*4, Agp + (size_t)srow[t]*DD + sc4[t]*4);
        cpasync16(sB + (uint32_t)(srow[t]*SP + sc4[t]*4)*4, Bgp + (size_t)srow[t]*DD + sc4[t]*4);
    }
    cp_commit();

    for (int kt = 0; kt < NT; kt++) {
        cp_wait<0>();
        __syncthreads();            // stage kt visible; prev compute done -> other buf reusable

        if (kt + 1 < NT) {
            int k0 = (kt + 1) * 32;
            uint32_t boff = (uint32_t)(((kt + 1) & 1) * 128 * SP) * 4;
#pragma unroll
            for (int t = 0; t < 4; t++) {
                cpasync16(sA + boff + (uint32_t)(srow[t]*SP + sc4[t]*4)*4,
                          Agp + (size_t)srow[t]*DD + k0 + sc4[t]*4);
                cpasync16(sB + boff + (uint32_t)(srow[t]*SP + sc4[t]*4)*4,
                          Bgp + (size_t)srow[t]*DD + k0 + sc4[t]*4);
            }
            cp_commit();
        }

        const float* Ab = As + (kt & 1) * 128 * SP;
        const float* Bb = Bs + (kt & 1) * 128 * SP;

#pragma unroll
        for (int ks = 0; ks < 4; ks++) {
            uint32_t af[4][4], bf[4][2];
#pragma unroll
            for (int mt = 0; mt < 4; mt++) {
                const float* ap = Ab + (warp_m*64 + mt*16 + g) * SP + ks*8 + c;
                af[mt][0] = __float_as_uint(ap[0]);
                af[mt][1] = __float_as_uint(ap[8*SP]);
                af[mt][2] = __float_as_uint(ap[4]);
                af[mt][3] = __float_as_uint(ap[8*SP + 4]);
            }
#pragma unroll
            for (int nt = 0; nt < 4; nt++) {
                const float* bp = Bb + (warp_n*32 + nt*8 + g) * SP + ks*8 + c;
                bf[nt][0] = __float_as_uint(bp[0]);
                bf[nt][1] = __float_as_uint(bp[4]);
            }
#pragma unroll
            for (int mt = 0; mt < 4; mt++)
#pragma unroll
                for (int nt = 0; nt < 4; nt++)
                    mma_tf32(acc[mt][nt], af[mt], bf[nt]);
        }
        __syncthreads();
    }

    // epilogue: bias add + store (float2 per row-half)
#pragma unroll
    for (int mt = 0; mt < 4; mt++) {
        int r0 = mBase + warp_m*64 + mt*16 + g;
#pragma unroll
        for (int nt = 0; nt < 4; nt++) {
            int gc = nBase + warp_n*32 + nt*8 + 2*c;
            float bz0 = bias[gc], bz1 = bias[gc+1];
            float2 v0 = make_float2(acc[mt][nt][0] + bz0, acc[mt][nt][1] + bz1);
            float2 v1 = make_float2(acc[mt][nt][2] + bz0, acc[mt][nt][3] + bz1);
            if (SCATTER) {
                int which = gc / 768;
                int rem = gc - which * 768;
                int h = rem >> 6, hd = rem & 63;
                float* dst = (which == 0) ? C0 : (which == 1 ? C1 : C2);
                int b0 = r0 >> 10, l0 = r0 & 1023;
                *(float2*)&dst[(size_t)((b0*HH + h)*LL + l0)*HD + hd] = v0;
                int r1 = r0 + 8;
                int b1 = r1 >> 10, l1 = r1 & 1023;
                *(float2*)&dst[(size_t)((b1*HH + h)*LL + l1)*HD + hd] = v1;
            } else {
                *(float2*)&C0[(size_t)r0 * N + gc] = v0;
                *(float2*)&C0[(size_t)(r0 + 8) * N + gc] = v1;
            }
        }
    }
}

// ---------------------------------------------------------------------------
// 4) Fused flash attention with positional bias table (unchanged).
//    Output tf32-rounded (A operand of GEMM2).
// ---------------------------------------------------------------------------
__global__ __launch_bounds__(256) void attn_kernel(float* __restrict__ out)
{
    extern __shared__ float smf[];
    float* Qs  = smf;                   // [128][68]
    float* Ks  = Qs  + 128*68;          // [64][68]
    float* Vs  = Ks  + 64*68;           // [64][68]
    float* Ps  = Vs  + 64*68;           // [128][68]
    float* tabs= Ps  + 128*68;          // [3969]

    int tid = threadIdx.x;
    int qt = blockIdx.x;
    int bh = blockIdx.y;
    int b = bh / HH, h = bh - b * HH;
    int q0 = qt * 128;

    const float* qg  = g_q + ((size_t)bh * LL + q0) * HD;
    const float* kgb = g_k + (size_t)bh * LL * HD;
    const float* vgb = g_v + (size_t)bh * LL * HD;

    for (int i = tid; i < 63*63; i += 256) tabs[i] = g_tab[h*4096 + i];
    for (int i = tid; i < 128*64; i += 256) Qs[(i>>6)*68 + (i&63)] = qg[i];

    int ty = tid >> 4, tx = tid & 15;
    int r0 = ty * 8, c0 = tx * 4;

    float m_i[8], l_i[8], acc_o[8][4];
#pragma unroll
    for (int i = 0; i < 8; i++) {
        m_i[i] = -1e30f; l_i[i] = 0.0f;
#pragma unroll
        for (int j = 0; j < 4; j++) acc_o[i][j] = 0.0f;
    }

    for (int k0 = 0; k0 < LL; k0 += 64) {
        __syncthreads();
        for (int i = tid; i < 64*64; i += 256) {
            int r = i >> 6, d = i & 63;
            Ks[r*68 + d] = kgb[(size_t)k0*HD + i];
            Vs[r*68 + d] = vgb[(size_t)k0*HD + i];
        }
        __syncthreads();

        float s[8][4];
#pragma unroll
        for (int i = 0; i < 8; i++)
#pragma unroll
            for (int j = 0; j < 4; j++) s[i][j] = 0.0f;

#pragma unroll 4
        for (int d = 0; d < 64; d++) {
            float af[8], bf[4];
#pragma unroll
            for (int i = 0; i < 8; i++) af[i] = Qs[(r0+i)*68 + d];
#pragma unroll
            for (int j = 0; j < 4; j++) bf[j] = Ks[(c0+j)*68 + d];
#pragma unroll
            for (int i = 0; i < 8; i++)
#pragma unroll
                for (int j = 0; j < 4; j++)
                    s[i][j] = fmaf(af[i], bf[j], s[i][j]);
        }

#pragma unroll
        for (int i = 0; i < 8; i++) {
            int q = q0 + r0 + i;
            int yq = q >> 5, xq = q & 31;
#pragma unroll
            for (int j = 0; j < 4; j++) {
                int k = k0 + c0 + j;
                int yk = k >> 5, xk = k & 31;
                s[i][j] = s[i][j] * 0.125f + tabs[(yq - yk + 31)*63 + (xq - xk + 31)];
            }
        }

#pragma unroll
        for (int i = 0; i < 8; i++) {
            float mx = fmaxf(fmaxf(s[i][0], s[i][1]), fmaxf(s[i][2], s[i][3]));
#pragma unroll
            for (int o = 8; o; o >>= 1) mx = fmaxf(mx, __shfl_xor_sync(0xffffffffu, mx, o));
            float mn = fmaxf(m_i[i], mx);
            float sc = __expf(m_i[i] - mn);
            float rs = 0.0f;
#pragma unroll
            for (int j = 0; j < 4; j++) {
                float pv = __expf(s[i][j] - mn);
                s[i][j] = pv;
                rs += pv;
            }
#pragma unroll
            for (int o = 8; o; o >>= 1) rs += __shfl_xor_sync(0xffffffffu, rs, o);
            l_i[i] = l_i[i] * sc + rs;
            m_i[i] = mn;
#pragma unroll
            for (int j = 0; j < 4; j++) acc_o[i][j] *= sc;
#pragma unroll
            for (int j = 0; j < 4; j++) Ps[(r0+i)*68 + c0 + j] = s[i][j];
        }
        __syncthreads();

#pragma unroll 2
        for (int kk = 0; kk < 64; kk++) {
            float pf[8], vf[4];
#pragma unroll
            for (int i = 0; i < 8; i++) pf[i] = Ps[(r0+i)*68 + kk];
#pragma unroll
            for (int j = 0; j < 4; j++) vf[j] = Vs[kk*68 + c0 + j];
#pragma unroll
            for (int i = 0; i < 8; i++)
#pragma unroll
                for (int j = 0; j < 4; j++)
                    acc_o[i][j] = fmaf(pf[i], vf[j], acc_o[i][j]);
        }
    }

#pragma unroll
    for (int i = 0; i < 8; i++) {
        float inv = 1.0f / l_i[i];
        int l = q0 + r0 + i;
#pragma unroll
        for (int j = 0; j < 4; j++)
            out[(size_t)(b*LL + l)*DD + h*HD + c0 + j] = to_tf32(acc_o[i][j] * inv);
    }
}

// ---------------------------------------------------------------------------
extern "C" void kernel_launch(void* const* d_in, const int* in_sizes, int n_in,
                              void* d_out, int out_size)
{
    const float* x     = (const float*)d_in[0];
    // d_in[1] = pos (32x32 grid, identical per batch — folded into table indexing)
    const float* wn    = (const float*)d_in[2];
    const float* w_in  = (const float*)d_in[3];
    const float* b_in  = (const float*)d_in[4];
    const float* w_out = (const float*)d_in[5];
    const float* b_out = (const float*)d_in[6];
    const float* bp    = (const float*)d_in[7];
    float* out = (float*)d_out;

    float *p_xn, *p_win, *p_wout, *p_q, *p_k, *p_v, *p_att;
    cudaGetSymbolAddress((void**)&p_xn,   g_xn);
    cudaGetSymbolAddress((void**)&p_win,  g_win);
    cudaGetSymbolAddress((void**)&p_wout, g_wout);
    cudaGetSymbolAddress((void**)&p_q,    g_q);
    cudaGetSymbolAddress((void**)&p_k,    g_k);
    cudaGetSymbolAddress((void**)&p_v,    g_v);
    cudaGetSymbolAddress((void**)&p_att,  g_att);

    bias_tab_kernel<<<HH, 256>>>(bp);
    cvt_tf32_kernel<<<(3*DD*DD + 255)/256, 256>>>(w_in,  p_win,  3*DD*DD);
    cvt_tf32_kernel<<<(DD*DD   + 255)/256, 256>>>(w_out, p_wout, DD*DD);
    rmsnorm_kernel<<<ROWS, 256>>>(x, wn);

    const int gemm_smem = 4 * 128 * SP * 4;   // 81920 B
    cudaFuncSetAttribute(gemm_mma<true>,  cudaFuncAttributeMaxDynamicSharedMemorySize, gemm_smem);
    cudaFuncSetAttribute(gemm_mma<false>, cudaFuncAttributeMaxDynamicSharedMemorySize, gemm_smem);

    gemm_mma<true><<<dim3(2304/128, ROWS/128), 256, gemm_smem>>>(p_xn, p_win, b_in, p_q, p_k, p_v, 2304);

    size_t smem = (size_t)(128*68 + 64*68 + 64*68 + 128*68 + 63*63) * sizeof(float);
    cudaFuncSetAttribute(attn_kernel, cudaFuncAttributeMaxDynamicSharedMemorySize, (int)smem);
    attn_kernel<<<dim3(LL/128, BB*HH), 256, smem>>>(p_att);

    gemm_mma<false><<<dim3(DD/128, ROWS/128), 256, gemm_smem>>>(p_att, p_wout, b_out, out, nullptr, nullptr, DD);
}

// round 5
// speedup vs baseline: 2.4208x; 1.5456x over previous
#include <cuda_runtime.h>
#include <math.h>
#include <stdint.h>

// Problem constants
#define BB 8
#define LL 1024
#define DD 768
#define HH 12
#define HD 64
#define ROWS (BB*LL)   // 8192

// Scratch (device globals: allocation-free rule)
__device__ float g_tab[HH*4096];          // per-head bias table [12][63*63]
__device__ float g_xn[ROWS*DD];           // tf32-rounded RMSNorm output
__device__ float g_win[3*DD*DD];          // tf32-rounded w_in
__device__ float g_wout[DD*DD];           // tf32-rounded w_out
__device__ float g_q[ROWS*DD];            // [B,H,L,HD], tf32-rounded
__device__ float g_k[ROWS*DD];
__device__ float g_v[ROWS*DD];
__device__ float g_att[ROWS*DD];          // [B,L,D], tf32-rounded

// ---------------------------------------------------------------------------
// helpers
// ---------------------------------------------------------------------------
__device__ __forceinline__ float to_tf32(float x) {
    uint32_t y;
    asm("cvt.rna.tf32.f32 %0, %1;" : "=r"(y) : "f"(x));
    return __uint_as_float(y);
}
__device__ __forceinline__ uint32_t smem_u32(const void* p) {
    uint32_t a;
    asm("{ .reg .u64 t; cvta.to.shared.u64 t, %1; cvt.u32.u64 %0, t; }" : "=r"(a) : "l"(p));
    return a;
}
__device__ __forceinline__ void cpasync16(uint32_t saddr, const void* g) {
    asm volatile("cp.async.cg.shared.global [%0], [%1], 16;" :: "r"(saddr), "l"(g));
}
__device__ __forceinline__ void cp_commit() {
    asm volatile("cp.async.commit_group;" ::: "memory");
}
template<int NN>
__device__ __forceinline__ void cp_wait() {
    asm volatile("cp.async.wait_group %0;" :: "n"(NN) : "memory");
}
__device__ __forceinline__ void mma_tf32(float* d, const uint32_t* a, const uint32_t* b) {
    asm volatile(
        "mma.sync.aligned.m16n8k8.row.col.f32.tf32.tf32.f32 "
        "{%0,%1,%2,%3}, {%4,%5,%6,%7}, {%8,%9}, {%0,%1,%2,%3};"
        : "+f"(d[0]), "+f"(d[1]), "+f"(d[2]), "+f"(d[3])
        : "r"(a[0]), "r"(a[1]), "r"(a[2]), "r"(a[3]), "r"(b[0]), "r"(b[1]));
}

// ---------------------------------------------------------------------------
// 0) tf32-round a weight matrix
// ---------------------------------------------------------------------------
__global__ void cvt_tf32_kernel(const float* __restrict__ src, float* __restrict__ dst, int n)
{
    int i = blockIdx.x * 256 + threadIdx.x;
    if (i < n) dst[i] = to_tf32(src[i]);
}

// ---------------------------------------------------------------------------
// 1) Per-head bias table over (dy,dx) in [-31,31]^2
// ---------------------------------------------------------------------------
__global__ void bias_tab_kernel(const float* __restrict__ bp)
{
    int h = blockIdx.x;
    float o  = bp[h*6+0];
    float c  = bp[h*6+1];
    float w  = bp[h*6+2];
    float p  = bp[h*6+3];
    float dl = bp[h*6+4];
    float m  = bp[h*6+5];
    float ac = fabsf(c);
    float am = fabsf(m);
    float at = fabsf(tanhf(dl));
    for (int i = threadIdx.x; i < 63*63; i += blockDim.x) {
        int dy = i / 63 - 31;
        int dx = i % 63 - 31;
        float fdy = (float)dy, fdx = (float)dx;
        float theta = atan2f(fdx, fdy);
        float r = sqrtf(fdy*fdy + fdx*fdx + 1e-12f);
        float t1 = powf(fmaxf(r - o, 0.0f), ac);
        float co = cosf((theta - p) * w * 0.5f);
        float t2 = 1.0f - at * powf(co*co, am);
        g_tab[h*4096 + i] = t1 * t2;
    }
}

// ---------------------------------------------------------------------------
// 2) RMSNorm: one block per row; output tf32-rounded (A operand of GEMM1)
// ---------------------------------------------------------------------------
__global__ __launch_bounds__(256) void rmsnorm_kernel(const float* __restrict__ x,
                                                      const float* __restrict__ wn)
{
    int row = blockIdx.x;
    const float* xr = x + (size_t)row * DD;
    float v[3];
    float s = 0.0f;
#pragma unroll
    for (int t = 0; t < 3; t++) {
        v[t] = xr[threadIdx.x + t*256];
        s += v[t]*v[t];
    }
#pragma unroll
    for (int o = 16; o; o >>= 1) s += __shfl_xor_sync(0xffffffffu, s, o);
    __shared__ float ws[8];
    __shared__ float rfac;
    int lane = threadIdx.x & 31, wid = threadIdx.x >> 5;
    if (lane == 0) ws[wid] = s;
    __syncthreads();
    if (threadIdx.x == 0) {
        float t = 0.0f;
#pragma unroll
        for (int i = 0; i < 8; i++) t += ws[i];
        rfac = rsqrtf(t * (1.0f/768.0f) + 1e-5f);
    }
    __syncthreads();
    float f = rfac;
#pragma unroll
    for (int t = 0; t < 3; t++) {
        int j = threadIdx.x + t*256;
        g_xn[(size_t)row*DD + j] = to_tf32(v[t] * f * wn[j]);
    }
}

// ---------------------------------------------------------------------------
// 3/5) tf32 mma.sync NT GEMM: C[M,N] = A[M,768] * Bw[N,768]^T + bias[N]
//      CTA 128x128, BK=32 double-buffered cp.async, 8 warps (2x4), warp 64x32.
//      SCATTER=true: scatter into q/k/v head-major buffers (tf32-rounded).
// ---------------------------------------------------------------------------
#define SP 40   // smem row stride (floats)

template<bool SCATTER>
__global__ __launch_bounds__(256) void gemm_mma(const float* __restrict__ A,
                                                const float* __restrict__ Bw,
                                                const float* __restrict__ bias,
                                                float* __restrict__ C0,
                                                float* __restrict__ C1,
                                                float* __restrict__ C2,
                                                int N)
{
    extern __shared__ float sm[];
    float* As = sm;                 // [2][128][SP]
    float* Bs = sm + 2*128*SP;      // [2][128][SP]
    uint32_t sA = smem_u32(As), sB = smem_u32(Bs);

    int tid = threadIdx.x;
    int wid = tid >> 5, lane = tid & 31;
    int warp_m = wid >> 2, warp_n = wid & 3;       // 2 x 4
    int g = lane >> 2, c = lane & 3;

    int mBase = blockIdx.y * 128, nBase = blockIdx.x * 128;

    int srow[4], sc4[4];
#pragma unroll
    for (int t = 0; t < 4; t++) {
        int i = tid + t*256;
        srow[t] = i >> 3;
        sc4[t]  = i & 7;
    }
    const float* Agp = A  + (size_t)mBase * DD;
    const float* Bgp = Bw + (size_t)nBase * DD;

    float acc[4][4][4];
#pragma unroll
    for (int mt = 0; mt < 4; mt++)
#pragma unroll
        for (int nt = 0; nt < 4; nt++)
#pragma unroll
            for (int r = 0; r < 4; r++) acc[mt][nt][r] = 0.0f;

    const int NT = DD / 32;   // 24

#pragma unroll
    for (int t = 0; t < 4; t++) {
        cpasync16(sA + (uint32_t)(srow[t]*SP + sc4[t]*4)*4, Agp + (size_t)srow[t]*DD + sc4[t]*4);
        cpasync16(sB + (uint32_t)(srow[t]*SP + sc4[t]*4)*4, Bgp + (size_t)srow[t]*DD + sc4[t]*4);
    }
    cp_commit();

    for (int kt = 0; kt < NT; kt++) {
        cp_wait<0>();
        __syncthreads();

        if (kt + 1 < NT) {
            int k0 = (kt + 1) * 32;
            uint32_t boff = (uint32_t)(((kt + 1) & 1) * 128 * SP) * 4;
#pragma unroll
            for (int t = 0; t < 4; t++) {
                cpasync16(sA + boff + (uint32_t)(srow[t]*SP + sc4[t]*4)*4,
                          Agp + (size_t)srow[t]*DD + k0 + sc4[t]*4);
                cpasync16(sB + boff + (uint32_t)(srow[t]*SP + sc4[t]*4)*4,
                          Bgp + (size_t)srow[t]*DD + k0 + sc4[t]*4);
            }
            cp_commit();
        }

        const float* Ab = As + (kt & 1) * 128 * SP;
        const float* Bb = Bs + (kt & 1) * 128 * SP;

#pragma unroll
        for (int ks = 0; ks < 4; ks++) {
            uint32_t af[4][4], bf[4][2];
#pragma unroll
            for (int mt = 0; mt < 4; mt++) {
                const float* ap = Ab + (warp_m*64 + mt*16 + g) * SP + ks*8 + c;
                af[mt][0] = __float_as_uint(ap[0]);
                af[mt][1] = __float_as_uint(ap[8*SP]);
                af[mt][2] = __float_as_uint(ap[4]);
                af[mt][3] = __float_as_uint(ap[8*SP + 4]);
            }
#pragma unroll
            for (int nt = 0; nt < 4; nt++) {
                const float* bp = Bb + (warp_n*32 + nt*8 + g) * SP + ks*8 + c;
                bf[nt][0] = __float_as_uint(bp[0]);
                bf[nt][1] = __float_as_uint(bp[4]);
            }
#pragma unroll
            for (int mt = 0; mt < 4; mt++)
#pragma unroll
                for (int nt = 0; nt < 4; nt++)
                    mma_tf32(acc[mt][nt], af[mt], bf[nt]);
        }
        __syncthreads();
    }

#pragma unroll
    for (int mt = 0; mt < 4; mt++) {
        int r0 = mBase + warp_m*64 + mt*16 + g;
#pragma unroll
        for (int nt = 0; nt < 4; nt++) {
            int gc = nBase + warp_n*32 + nt*8 + 2*c;
            float bz0 = bias[gc], bz1 = bias[gc+1];
            if (SCATTER) {
                float2 v0 = make_float2(to_tf32(acc[mt][nt][0] + bz0), to_tf32(acc[mt][nt][1] + bz1));
                float2 v1 = make_float2(to_tf32(acc[mt][nt][2] + bz0), to_tf32(acc[mt][nt][3] + bz1));
                int which = gc / 768;
                int rem = gc - which * 768;
                int h = rem >> 6, hd = rem & 63;
                float* dst = (which == 0) ? C0 : (which == 1 ? C1 : C2);
                int b0 = r0 >> 10, l0 = r0 & 1023;
                *(float2*)&dst[(size_t)((b0*HH + h)*LL + l0)*HD + hd] = v0;
                int r1 = r0 + 8;
                int b1 = r1 >> 10, l1 = r1 & 1023;
                *(float2*)&dst[(size_t)((b1*HH + h)*LL + l1)*HD + hd] = v1;
            } else {
                float2 v0 = make_float2(acc[mt][nt][0] + bz0, acc[mt][nt][1] + bz1);
                float2 v1 = make_float2(acc[mt][nt][2] + bz0, acc[mt][nt][3] + bz1);
                *(float2*)&C0[(size_t)r0 * N + gc] = v0;
                *(float2*)&C0[(size_t)(r0 + 8) * N + gc] = v1;
            }
        }
    }
}

// ---------------------------------------------------------------------------
// 4) Flash attention, tensor-core edition.
//    Grid (L/128, B*H), 256 threads = 8 warps; warp w owns rows 16w..16w+15.
//    K-tile = 64 keys. Q frags register-resident; P staged via smem (pitch 68).
// ---------------------------------------------------------------------------
__global__ __launch_bounds__(256) void attn_mma_kernel(float* __restrict__ out)
{
    extern __shared__ float smf[];
    float* Ks   = smf;                  // [64][68]
    float* Vs   = Ks + 64*68;           // [64][68]
    float* Ps   = Vs + 64*68;           // [128][68]  (also Q staging)
    float* tabs = Ps + 128*68;          // [3969]

    int tid = threadIdx.x;
    int wid = tid >> 5, lane = tid & 31;
    int g = lane >> 2, c = lane & 3;
    int qt = blockIdx.x, bh = blockIdx.y;
    int b = bh / HH, h = bh - b * HH;
    int q0 = qt * 128;

    const float* qg = g_q + ((size_t)bh * LL + q0) * HD;
    const float* kg = g_k + (size_t)bh * LL * HD;
    const float* vg = g_v + (size_t)bh * LL * HD;

    for (int i = tid; i < 63*63; i += 256) tabs[i] = g_tab[h*4096 + i];
    for (int i = tid*4; i < 128*64; i += 1024) {
        int r = i >> 6, d = i & 63;
        *(float4*)&Ps[r*68 + d] = *(const float4*)(qg + i);
    }
    __syncthreads();

    // Q fragments: rows 16*wid+g, +8; 8 k-steps of 8
    uint32_t qf[8][4];
    {
        const float* qp = Ps + (16*wid + g)*68 + c;
#pragma unroll
        for (int ks = 0; ks < 8; ks++) {
            qf[ks][0] = __float_as_uint(qp[ks*8]);
            qf[ks][1] = __float_as_uint(qp[8*68 + ks*8]);
            qf[ks][2] = __float_as_uint(qp[ks*8 + 4]);
            qf[ks][3] = __float_as_uint(qp[8*68 + ks*8 + 4]);
        }
    }

    int qrow0 = q0 + 16*wid + g, qrow1 = qrow0 + 8;
    int yq0 = qrow0 >> 5, xq0 = qrow0 & 31;
    int yq1 = qrow1 >> 5, xq1 = qrow1 & 31;

    float m0 = -1e30f, m1 = -1e30f, l0 = 0.0f, l1 = 0.0f;
    float o_acc[8][4];
#pragma unroll
    for (int nt = 0; nt < 8; nt++)
#pragma unroll
        for (int r = 0; r < 4; r++) o_acc[nt][r] = 0.0f;

    for (int k0 = 0; k0 < LL; k0 += 64) {
        __syncthreads();   // prev P.V done before K/V/P overwrite (covers Q-frag reads on iter 0)
        for (int i = tid*4; i < 64*64; i += 1024) {
            int r = i >> 6, d = i & 63;
            *(float4*)&Ks[r*68 + d] = *(const float4*)(kg + (size_t)k0*HD + i);
            *(float4*)&Vs[r*68 + d] = *(const float4*)(vg + (size_t)k0*HD + i);
        }
        __syncthreads();

        // S = Q K^T  (warp strip 16 x 64)
        float s[8][4];
#pragma unroll
        for (int nt = 0; nt < 8; nt++)
#pragma unroll
            for (int r = 0; r < 4; r++) s[nt][r] = 0.0f;

#pragma unroll
        for (int ks = 0; ks < 8; ks++) {
#pragma unroll
            for (int nt = 0; nt < 8; nt++) {
                uint32_t bfr[2];
                const float* bp = Ks + (nt*8 + g)*68 + ks*8 + c;
                bfr[0] = __float_as_uint(bp[0]);
                bfr[1] = __float_as_uint(bp[4]);
                mma_tf32(s[nt], qf[ks], bfr);
            }
        }

        // scale + bias; running max
        float mx0 = -1e30f, mx1 = -1e30f;
#pragma unroll
        for (int nt = 0; nt < 8; nt++) {
            int k = k0 + nt*8 + 2*c;
            int yk = k >> 5, xk = k & 31;      // xk <= 30, so xk+1 never wraps
            const float* t0 = tabs + (yq0 - yk + 31)*63 + (xq0 - xk + 31);
            const float* t1 = tabs + (yq1 - yk + 31)*63 + (xq1 - xk + 31);
            s[nt][0] = s[nt][0]*0.125f + t0[0];
            s[nt][1] = s[nt][1]*0.125f + t0[-1];
            s[nt][2] = s[nt][2]*0.125f + t1[0];
            s[nt][3] = s[nt][3]*0.125f + t1[-1];
            mx0 = fmaxf(mx0, fmaxf(s[nt][0], s[nt][1]));
            mx1 = fmaxf(mx1, fmaxf(s[nt][2], s[nt][3]));
        }
        mx0 = fmaxf(mx0, __shfl_xor_sync(0xffffffffu, mx0, 1));
        mx0 = fmaxf(mx0, __shfl_xor_sync(0xffffffffu, mx0, 2));
        mx1 = fmaxf(mx1, __shfl_xor_sync(0xffffffffu, mx1, 1));
        mx1 = fmaxf(mx1, __shfl_xor_sync(0xffffffffu, mx1, 2));

        float mn0 = fmaxf(m0, mx0), mn1 = fmaxf(m1, mx1);
        float sc0 = __expf(m0 - mn0), sc1 = __expf(m1 - mn1);
        float rs0 = 0.0f, rs1 = 0.0f;
#pragma unroll
        for (int nt = 0; nt < 8; nt++) {
            s[nt][0] = __expf(s[nt][0] - mn0);
            s[nt][1] = __expf(s[nt][1] - mn0);
            s[nt][2] = __expf(s[nt][2] - mn1);
            s[nt][3] = __expf(s[nt][3] - mn1);
            rs0 += s[nt][0] + s[nt][1];
            rs1 += s[nt][2] + s[nt][3];
        }
        rs0 += __shfl_xor_sync(0xffffffffu, rs0, 1);
        rs0 += __shfl_xor_sync(0xffffffffu, rs0, 2);
        rs1 += __shfl_xor_sync(0xffffffffu, rs1, 1);
        rs1 += __shfl_xor_sync(0xffffffffu, rs1, 2);
        l0 = l0*sc0 + rs0; m0 = mn0;
        l1 = l1*sc1 + rs1; m1 = mn1;

#pragma unroll
        for (int nt = 0; nt < 8; nt++) {
            o_acc[nt][0] *= sc0; o_acc[nt][1] *= sc0;
            o_acc[nt][2] *= sc1; o_acc[nt][3] *= sc1;
            // stage P (tf32-rounded) for the P.V mma
            float2 p0 = make_float2(to_tf32(s[nt][0]), to_tf32(s[nt][1]));
            float2 p1 = make_float2(to_tf32(s[nt][2]), to_tf32(s[nt][3]));
            *(float2*)&Ps[(16*wid + g)*68 + nt*8 + 2*c]     = p0;
            *(float2*)&Ps[(16*wid + g + 8)*68 + nt*8 + 2*c] = p1;
        }
        __syncthreads();

        // O += P V
#pragma unroll
        for (int ks = 0; ks < 8; ks++) {
            uint32_t af[4];
            const float* ap = Ps + (16*wid + g)*68 + ks*8 + c;
            af[0] = __float_as_uint(ap[0]);
            af[1] = __float_as_uint(ap[8*68]);
            af[2] = __float_as_uint(ap[4]);
            af[3] = __float_as_uint(ap[8*68 + 4]);
#pragma unroll
            for (int nt = 0; nt < 8; nt++) {
                uint32_t bfr[2];
                const float* bp = Vs + (ks*8 + c)*68 + nt*8 + g;
                bfr[0] = __float_as_uint(bp[0]);
                bfr[1] = __float_as_uint(bp[4*68]);
                mma_tf32(o_acc[nt], af, bfr);
            }
        }
    }

    // normalize + write [B,L,D] (tf32-rounded: feeds out-proj A operand)
    float inv0 = 1.0f / l0, inv1 = 1.0f / l1;
    int lr0 = q0 + 16*wid + g, lr1 = lr0 + 8;
#pragma unroll
    for (int nt = 0; nt < 8; nt++) {
        int d = h*HD + nt*8 + 2*c;
        float2 v0 = make_float2(to_tf32(o_acc[nt][0]*inv0), to_tf32(o_acc[nt][1]*inv0));
        float2 v1 = make_float2(to_tf32(o_acc[nt][2]*inv1), to_tf32(o_acc[nt][3]*inv1));
        *(float2*)&out[(size_t)(b*LL + lr0)*DD + d] = v0;
        *(float2*)&out[(size_t)(b*LL + lr1)*DD + d] = v1;
    }
}

// ---------------------------------------------------------------------------
extern "C" void kernel_launch(void* const* d_in, const int* in_sizes, int n_in,
                              void* d_out, int out_size)
{
    const float* x     = (const float*)d_in[0];
    // d_in[1] = pos (32x32 grid, identical per batch — folded into table indexing)
    const float* wn    = (const float*)d_in[2];
    const float* w_in  = (const float*)d_in[3];
    const float* b_in  = (const float*)d_in[4];
    const float* w_out = (const float*)d_in[5];
    const float* b_out = (const float*)d_in[6];
    const float* bp    = (const float*)d_in[7];
    float* out = (float*)d_out;

    float *p_xn, *p_win, *p_wout, *p_q, *p_k, *p_v, *p_att;
    cudaGetSymbolAddress((void**)&p_xn,   g_xn);
    cudaGetSymbolAddress((void**)&p_win,  g_win);
    cudaGetSymbolAddress((void**)&p_wout, g_wout);
    cudaGetSymbolAddress((void**)&p_q,    g_q);
    cudaGetSymbolAddress((void**)&p_k,    g_k);
    cudaGetSymbolAddress((void**)&p_v,    g_v);
    cudaGetSymbolAddress((void**)&p_att,  g_att);

    bias_tab_kernel<<<HH, 256>>>(bp);
    cvt_tf32_kernel<<<(3*DD*DD + 255)/256, 256>>>(w_in,  p_win,  3*DD*DD);
    cvt_tf32_kernel<<<(DD*DD   + 255)/256, 256>>>(w_out, p_wout, DD*DD);
    rmsnorm_kernel<<<ROWS, 256>>>(x, wn);

    const int gemm_smem = 4 * 128 * SP * 4;   // 81920 B
    cudaFuncSetAttribute(gemm_mma<true>,  cudaFuncAttributeMaxDynamicSharedMemorySize, gemm_smem);
    cudaFuncSetAttribute(gemm_mma<false>, cudaFuncAttributeMaxDynamicSharedMemorySize, gemm_smem);

    gemm_mma<true><<<dim3(2304/128, ROWS/128), 256, gemm_smem>>>(p_xn, p_win, b_in, p_q, p_k, p_v, 2304);

    const int attn_smem = (64*68 + 64*68 + 128*68 + 3969) * 4;   // 85508 B
    cudaFuncSetAttribute(attn_mma_kernel, cudaFuncAttributeMaxDynamicSharedMemorySize, attn_smem);
    attn_mma_kernel<<<dim3(LL/128, BB*HH), 256, attn_smem>>>(p_att);

    gemm_mma<false><<<dim3(DD/128, ROWS/128), 256, gemm_smem>>>(p_att, p_wout, b_out, out, nullptr, nullptr, DD);
}

// round 7
// speedup vs baseline: 4.9409x; 2.0410x over previous
#include <cuda_runtime.h>
#include <cuda_fp16.h>
#include <math.h>
#include <stdint.h>

// Problem constants
#define BB 8
#define LL 1024
#define DD 768
#define HH 12
#define HD 64
#define ROWS (BB*LL)   // 8192

// Scratch (device globals: allocation-free rule)
__device__ float  g_tab[HH*4096];         // per-head bias table [12][63*63]
__device__ float  g_xn[ROWS*DD];          // tf32-rounded RMSNorm output
__device__ float  g_win[3*DD*DD];         // tf32-rounded w_in
__device__ float  g_wout[DD*DD];          // tf32-rounded w_out
__device__ __half g_q[ROWS*DD];           // [B,H,L,HD], fp16, pre-scaled by 0.125
__device__ __half g_k[ROWS*DD];           // fp16
__device__ __half g_v[ROWS*DD];           // fp16
__device__ float  g_att[ROWS*DD];         // [B,L,D], tf32-rounded

// ---------------------------------------------------------------------------
// helpers
// ---------------------------------------------------------------------------
__device__ __forceinline__ float to_tf32(float x) {
    uint32_t y;
    asm("cvt.rna.tf32.f32 %0, %1;" : "=r"(y) : "f"(x));
    return __uint_as_float(y);
}
__device__ __forceinline__ uint32_t smem_u32(const void* p) {
    uint32_t a;
    asm("{ .reg .u64 t; cvta.to.shared.u64 t, %1; cvt.u32.u64 %0, t; }" : "=r"(a) : "l"(p));
    return a;
}
__device__ __forceinline__ void cpasync16(uint32_t saddr, const void* g) {
    asm volatile("cp.async.cg.shared.global [%0], [%1], 16;" :: "r"(saddr), "l"(g));
}
__device__ __forceinline__ void cp_commit() {
    asm volatile("cp.async.commit_group;" ::: "memory");
}
template<int NN>
__device__ __forceinline__ void cp_wait() {
    asm volatile("cp.async.wait_group %0;" :: "n"(NN) : "memory");
}
__device__ __forceinline__ void mma_tf32(float* d, const uint32_t* a, const uint32_t* b) {
    asm volatile(
        "mma.sync.aligned.m16n8k8.row.col.f32.tf32.tf32.f32 "
        "{%0,%1,%2,%3}, {%4,%5,%6,%7}, {%8,%9}, {%0,%1,%2,%3};"
        : "+f"(d[0]), "+f"(d[1]), "+f"(d[2]), "+f"(d[3])
        : "r"(a[0]), "r"(a[1]), "r"(a[2]), "r"(a[3]), "r"(b[0]), "r"(b[1]));
}
__device__ __forceinline__ void mma_f16(float* d, const uint32_t* a, uint32_t b0, uint32_t b1) {
    asm volatile(
        "mma.sync.aligned.m16n8k16.row.col.f32.f16.f16.f32 "
        "{%0,%1,%2,%3}, {%4,%5,%6,%7}, {%8,%9}, {%0,%1,%2,%3};"
        : "+f"(d[0]), "+f"(d[1]), "+f"(d[2]), "+f"(d[3])
        : "r"(a[0]), "r"(a[1]), "r"(a[2]), "r"(a[3]), "r"(b0), "r"(b1));
}
__device__ __forceinline__ void ldm4(uint32_t* f, uint32_t a) {
    asm volatile("ldmatrix.sync.aligned.m8n8.x4.shared.b16 {%0,%1,%2,%3}, [%4];"
                 : "=r"(f[0]), "=r"(f[1]), "=r"(f[2]), "=r"(f[3]) : "r"(a));
}
__device__ __forceinline__ void ldm4t(uint32_t* f, uint32_t a) {
    asm volatile("ldmatrix.sync.aligned.m8n8.x4.trans.shared.b16 {%0,%1,%2,%3}, [%4];"
                 : "=r"(f[0]), "=r"(f[1]), "=r"(f[2]), "=r"(f[3]) : "r"(a));
}

// ---------------------------------------------------------------------------
// 0) tf32-round a weight matrix
// ---------------------------------------------------------------------------
__global__ void cvt_tf32_kernel(const float* __restrict__ src, float* __restrict__ dst, int n)
{
    int i = blockIdx.x * 256 + threadIdx.x;
    if (i < n) dst[i] = to_tf32(src[i]);
}

// ---------------------------------------------------------------------------
// 1) Per-head bias table over (dy,dx) in [-31,31]^2
// ---------------------------------------------------------------------------
__global__ void bias_tab_kernel(const float* __restrict__ bp)
{
    int h = blockIdx.x;
    float o  = bp[h*6+0];
    float c  = bp[h*6+1];
    float w  = bp[h*6+2];
    float p  = bp[h*6+3];
    float dl = bp[h*6+4];
    float m  = bp[h*6+5];
    float ac = fabsf(c);
    float am = fabsf(m);
    float at = fabsf(tanhf(dl));
    for (int i = threadIdx.x; i < 63*63; i += blockDim.x) {
        int dy = i / 63 - 31;
        int dx = i % 63 - 31;
        float fdy = (float)dy, fdx = (float)dx;
        float theta = atan2f(fdx, fdy);
        float r = sqrtf(fdy*fdy + fdx*fdx + 1e-12f);
        float t1 = powf(fmaxf(r - o, 0.0f), ac);
        float co = cosf((theta - p) * w * 0.5f);
        float t2 = 1.0f - at * powf(co*co, am);
        g_tab[h*4096 + i] = t1 * t2;
    }
}

// ---------------------------------------------------------------------------
// 2) RMSNorm: one block per row; output tf32-rounded (A operand of GEMM1)
// ---------------------------------------------------------------------------
__global__ __launch_bounds__(256) void rmsnorm_kernel(const float* __restrict__ x,
                                                      const float* __restrict__ wn)
{
    int row = blockIdx.x;
    const float* xr = x + (size_t)row * DD;
    float v[3];
    float s = 0.0f;
#pragma unroll
    for (int t = 0; t < 3; t++) {
        v[t] = xr[threadIdx.x + t*256];
        s += v[t]*v[t];
    }
#pragma unroll
    for (int o = 16; o; o >>= 1) s += __shfl_xor_sync(0xffffffffu, s, o);
    __shared__ float ws[8];
    __shared__ float rfac;
    int lane = threadIdx.x & 31, wid = threadIdx.x >> 5;
    if (lane == 0) ws[wid] = s;
    __syncthreads();
    if (threadIdx.x == 0) {
        float t = 0.0f;
#pragma unroll
        for (int i = 0; i < 8; i++) t += ws[i];
        rfac = rsqrtf(t * (1.0f/768.0f) + 1e-5f);
    }
    __syncthreads();
    float f = rfac;
#pragma unroll
    for (int t = 0; t < 3; t++) {
        int j = threadIdx.x + t*256;
        g_xn[(size_t)row*DD + j] = to_tf32(v[t] * f * wn[j]);
    }
}

// ---------------------------------------------------------------------------
// 3/5) tf32 mma.sync NT GEMM: C[M,N] = A[M,768] * Bw[N,768]^T + bias[N]
//      CTA 128x128, BK=32 double-buffered cp.async, 8 warps (2x4), warp 64x32.
//      SCATTER=true: half2 scatter into q/k/v head-major buffers (q scaled 1/8).
// ---------------------------------------------------------------------------
#define SP 40   // smem row stride (floats)

template<bool SCATTER>
__global__ __launch_bounds__(256) void gemm_mma(const float* __restrict__ A,
                                                const float* __restrict__ Bw,
                                                const float* __restrict__ bias,
                                                float* __restrict__ Cf,
                                                __half* __restrict__ Qh,
                                                __half* __restrict__ Kh,
                                                __half* __restrict__ Vh,
                                                int N)
{
    extern __shared__ float sm[];
    float* As = sm;                 // [2][128][SP]
    float* Bs = sm + 2*128*SP;      // [2][128][SP]
    uint32_t sA = smem_u32(As), sB = smem_u32(Bs);

    int tid = threadIdx.x;
    int wid = tid >> 5, lane = tid & 31;
    int warp_m = wid >> 2, warp_n = wid & 3;       // 2 x 4
    int g = lane >> 2, c = lane & 3;

    int mBase = blockIdx.y * 128, nBase = blockIdx.x * 128;

    int srow[4], sc4[4];
#pragma unroll
    for (int t = 0; t < 4; t++) {
        int i = tid + t*256;
        srow[t] = i >> 3;
        sc4[t]  = i & 7;
    }
    const float* Agp = A  + (size_t)mBase * DD;
    const float* Bgp = Bw + (size_t)nBase * DD;

    float acc[4][4][4];
#pragma unroll
    for (int mt = 0; mt < 4; mt++)
#pragma unroll
        for (int nt = 0; nt < 4; nt++)
#pragma unroll
            for (int r = 0; r < 4; r++) acc[mt][nt][r] = 0.0f;

    const int NT = DD / 32;   // 24

#pragma unroll
    for (int t = 0; t < 4; t++) {
        cpasync16(sA + (uint32_t)(srow[t]*SP + sc4[t]*4)*4, Agp + (size_t)srow[t]*DD + sc4[t]*4);
        cpasync16(sB + (uint32_t)(srow[t]*SP + sc4[t]*4)*4, Bgp + (size_t)srow[t]*DD + sc4[t]*4);
    }
    cp_commit();

    for (int kt = 0; kt < NT; kt++) {
        cp_wait<0>();
        __syncthreads();

        if (kt + 1 < NT) {
            int k0 = (kt + 1) * 32;
            uint32_t boff = (uint32_t)(((kt + 1) & 1) * 128 * SP) * 4;
#pragma unroll
            for (int t = 0; t < 4; t++) {
                cpasync16(sA + boff + (uint32_t)(srow[t]*SP + sc4[t]*4)*4,
                          Agp + (size_t)srow[t]*DD + k0 + sc4[t]*4);
                cpasync16(sB + boff + (uint32_t)(srow[t]*SP + sc4[t]*4)*4,
                          Bgp + (size_t)srow[t]*DD + k0 + sc4[t]*4);
            }
            cp_commit();
        }

        const float* Ab = As + (kt & 1) * 128 * SP;
        const float* Bb = Bs + (kt & 1) * 128 * SP;

#pragma unroll
        for (int ks = 0; ks < 4; ks++) {
            uint32_t af[4][4], bf[4][2];
#pragma unroll
            for (int mt = 0; mt < 4; mt++) {
                const float* ap = Ab + (warp_m*64 + mt*16 + g) * SP + ks*8 + c;
                af[mt][0] = __float_as_uint(ap[0]);
                af[mt][1] = __float_as_uint(ap[8*SP]);
                af[mt][2] = __float_as_uint(ap[4]);
                af[mt][3] = __float_as_uint(ap[8*SP + 4]);
            }
#pragma unroll
            for (int nt = 0; nt < 4; nt++) {
                const float* bp = Bb + (warp_n*32 + nt*8 + g) * SP + ks*8 + c;
                bf[nt][0] = __float_as_uint(bp[0]);
                bf[nt][1] = __float_as_uint(bp[4]);
            }
#pragma unroll
            for (int mt = 0; mt < 4; mt++)
#pragma unroll
                for (int nt = 0; nt < 4; nt++)
                    mma_tf32(acc[mt][nt], af[mt], bf[nt]);
        }
        __syncthreads();
    }

#pragma unroll
    for (int mt = 0; mt < 4; mt++) {
        int r0 = mBase + warp_m*64 + mt*16 + g;
#pragma unroll
        for (int nt = 0; nt < 4; nt++) {
            int gc = nBase + warp_n*32 + nt*8 + 2*c;
            float bz0 = bias[gc], bz1 = bias[gc+1];
            if (SCATTER) {
                int which = gc / 768;
                int rem = gc - which * 768;
                int h = rem >> 6, hd = rem & 63;
                float sc = (which == 0) ? 0.125f : 1.0f;   // fold 1/sqrt(64) into Q
                __half* dst = (which == 0) ? Qh : (which == 1 ? Kh : Vh);
                __half2 v0 = __floats2half2_rn((acc[mt][nt][0] + bz0)*sc, (acc[mt][nt][1] + bz1)*sc);
                __half2 v1 = __floats2half2_rn((acc[mt][nt][2] + bz0)*sc, (acc[mt][nt][3] + bz1)*sc);
                int b0 = r0 >> 10, l0 = r0 & 1023;
                *(__half2*)&dst[(size_t)((b0*HH + h)*LL + l0)*HD + hd] = v0;
                int r1 = r0 + 8;
                int b1 = r1 >> 10, l1 = r1 & 1023;
                *(__half2*)&dst[(size_t)((b1*HH + h)*LL + l1)*HD + hd] = v1;
            } else {
                float2 v0 = make_float2(acc[mt][nt][0] + bz0, acc[mt][nt][1] + bz1);
                float2 v1 = make_float2(acc[mt][nt][2] + bz0, acc[mt][nt][3] + bz1);
                *(float2*)&Cf[(size_t)r0 * N + gc] = v0;
                *(float2*)&Cf[(size_t)(r0 + 8) * N + gc] = v1;
            }
        }
    }
}

// ---------------------------------------------------------------------------
// 4) Flash attention, fp16 m16n8k16 + ldmatrix edition.
//    Grid (8, 96), 256 threads = 8 warps; warp w owns q rows 16w..16w+15.
//    K-tile = 64 keys, double-buffered via cp.async.
//    Smem tile layout: [row][chunk] with chunk ^= (row&7), 128B rows (64 half).
// ---------------------------------------------------------------------------
__global__ __launch_bounds__(256) void attn_h_kernel(float* __restrict__ out)
{
    extern __shared__ __align__(128) char smc[];
    // Kbuf: smc + {0,8192}; Vbuf: smc+16384 + {0,8192}; P/Q: smc+32768 (16KB); tabs: smc+49152
    char*  Pbase = smc + 32768;
    float* tabs  = (float*)(smc + 49152);

    int tid = threadIdx.x;
    int wid = tid >> 5, lane = tid & 31;
    int g = lane >> 2, c = lane & 3;
    int mi = lane >> 3, r = lane & 7;       // ldmatrix lane mapping
    int qt = blockIdx.x, bh = blockIdx.y;
    int b = bh / HH, h = bh - b * HH;
    int q0 = qt * 128;

    const __half* qg = g_q + ((size_t)bh * LL + q0) * HD;
    const __half* kg = g_k + (size_t)bh * LL * HD;
    const __half* vg = g_v + (size_t)bh * LL * HD;

    uint32_t kBase = smem_u32(smc);
    uint32_t vBase = smem_u32(smc + 16384);
    uint32_t pB    = smem_u32(Pbase);

    // Stage Q (128x64 half) into P area, swizzled  [group 0]
#pragma unroll
    for (int it = 0; it < 4; it++) {
        int i = tid + it*256;                  // 1024 chunks
        int row = i >> 3, ch = i & 7;
        cpasync16(pB + row*128 + ((ch ^ (row & 7)) << 4), qg + row*64 + ch*8);
    }
    cp_commit();
    // Prefetch K/V tile 0  [group 1]
#pragma unroll
    for (int it = 0; it < 2; it++) {
        int i = tid + it*256;                  // 512 chunks each
        int row = i >> 3, ch = i & 7;
        uint32_t so = row*128 + ((ch ^ (row & 7)) << 4);
        cpasync16(kBase + so, kg + row*64 + ch*8);
        cpasync16(vBase + so, vg + row*64 + ch*8);
    }
    cp_commit();
    // bias table
    for (int i = tid; i < 63*63; i += 256) tabs[i] = g_tab[h*4096 + i];

    cp_wait<1>();          // Q landed (K/V0 may still be in flight)
    __syncthreads();

    // Q fragments: 4 k16-steps, register resident
    uint32_t qf[4][4];
    {
        int rowq = 16*wid + (mi & 1)*8 + r;
#pragma unroll
        for (int ks = 0; ks < 4; ks++) {
            int ch = 2*ks + (mi >> 1);
            ldm4(qf[ks], pB + rowq*128 + ((ch ^ r) << 4));
        }
    }

    // per-thread bias-table pointers (xk invariant across tiles; yk steps 2/tile)
    int qr0 = q0 + 16*wid + g, qr1 = qr0 + 8;
    const float* ptA = tabs + ((qr0 >> 5) + 31)*63 + (qr0 & 31) + 31 - 2*c;
    const float* ptB = tabs + ((qr1 >> 5) + 31)*63 + (qr1 & 31) + 31 - 2*c;

    float m0 = -1e30f, m1 = -1e30f, l0 = 0.0f, l1 = 0.0f;
    float o_acc[8][4];
#pragma unroll
    for (int nt = 0; nt < 8; nt++)
#pragma unroll
        for (int k = 0; k < 4; k++) o_acc[nt][k] = 0.0f;

    for (int t = 0; t < 16; t++) {
        uint32_t kB = kBase + (t & 1)*8192;
        uint32_t vB = vBase + (t & 1)*8192;
        cp_wait<0>();
        __syncthreads();     // tile t visible; everyone done with buffer (t+1)&1

        if (t + 1 < 16) {
            int kr0 = (t + 1) * 64;
            uint32_t kBn = kBase + ((t + 1) & 1)*8192;
            uint32_t vBn = vBase + ((t + 1) & 1)*8192;
#pragma unroll
            for (int it = 0; it < 2; it++) {
                int i = tid + it*256;
                int row = i >> 3, ch = i & 7;
                uint32_t so = row*128 + ((ch ^ (row & 7)) << 4);
                cpasync16(kBn + so, kg + (size_t)(kr0 + row)*64 + ch*8);
                cpasync16(vBn + so, vg + (size_t)(kr0 + row)*64 + ch*8);
            }
            cp_commit();
        }

        // ---- S = Q K^T  (16 x 64 per warp) ----
        float s[8][4];
#pragma unroll
        for (int nt = 0; nt < 8; nt++)
#pragma unroll
            for (int k = 0; k < 4; k++) s[nt][k] = 0.0f;

#pragma unroll
        for (int ks = 0; ks < 4; ks++) {
            uint32_t kr[4][4];
#pragma unroll
            for (int p = 0; p < 4; p++) {
                int keyrow = 16*p + (mi & 1)*8 + r;
                int ch = 2*ks + (mi >> 1);
                ldm4(kr[p], kB + keyrow*128 + ((ch ^ r) << 4));
            }
#pragma unroll
            for (int p = 0; p < 4; p++) {
                mma_f16(s[2*p],   qf[ks], kr[p][0], kr[p][2]);
                mma_f16(s[2*p+1], qf[ks], kr[p][1], kr[p][3]);
            }
        }

        // ---- bias + online softmax ----
        float mx0 = -1e30f, mx1 = -1e30f;
#pragma unroll
        for (int nt = 0; nt < 8; nt++) {
            const int off = (nt < 4) ? (-8*nt) : (32 - 8*nt - 63);
            s[nt][0] += ptA[off];
            s[nt][1] += ptA[off - 1];
            s[nt][2] += ptB[off];
            s[nt][3] += ptB[off - 1];
            mx0 = fmaxf(mx0, fmaxf(s[nt][0], s[nt][1]));
            mx1 = fmaxf(mx1, fmaxf(s[nt][2], s[nt][3]));
        }
        ptA -= 126; ptB -= 126;
        mx0 = fmaxf(mx0, __shfl_xor_sync(0xffffffffu, mx0, 1));
        mx0 = fmaxf(mx0, __shfl_xor_sync(0xffffffffu, mx0, 2));
        mx1 = fmaxf(mx1, __shfl_xor_sync(0xffffffffu, mx1, 1));
        mx1 = fmaxf(mx1, __shfl_xor_sync(0xffffffffu, mx1, 2));

        float mn0 = fmaxf(m0, mx0), mn1 = fmaxf(m1, mx1);
        float sc0 = __expf(m0 - mn0), sc1 = __expf(m1 - mn1);
        float rs0 = 0.0f, rs1 = 0.0f;
#pragma unroll
        for (int nt = 0; nt < 8; nt++) {
            s[nt][0] = __expf(s[nt][0] - mn0);
            s[nt][1] = __expf(s[nt][1] - mn0);
            s[nt][2] = __expf(s[nt][2] - mn1);
            s[nt][3] = __expf(s[nt][3] - mn1);
            rs0 += s[nt][0] + s[nt][1];
            rs1 += s[nt][2] + s[nt][3];
        }
        rs0 += __shfl_xor_sync(0xffffffffu, rs0, 1);
        rs0 += __shfl_xor_sync(0xffffffffu, rs0, 2);
        rs1 += __shfl_xor_sync(0xffffffffu, rs1, 1);
        rs1 += __shfl_xor_sync(0xffffffffu, rs1, 2);
        l0 = l0*sc0 + rs0; m0 = mn0;
        l1 = l1*sc1 + rs1; m1 = mn1;

        // scale O, store P (half2, swizzled; own rows only -> no extra sync)
        int rowp0 = 16*wid + g;
#pragma unroll
        for (int nt = 0; nt < 8; nt++) {
            o_acc[nt][0] *= sc0; o_acc[nt][1] *= sc0;
            o_acc[nt][2] *= sc1; o_acc[nt][3] *= sc1;
            uint32_t soff = ((nt ^ g) << 4) + 4*c;
            *(__half2*)(Pbase + rowp0*128 + soff)       = __floats2half2_rn(s[nt][0], s[nt][1]);
            *(__half2*)(Pbase + (rowp0 + 8)*128 + soff) = __floats2half2_rn(s[nt][2], s[nt][3]);
        }

        // ---- O += P V ----
#pragma unroll
        for (int ks = 0; ks < 4; ks++) {
            uint32_t pa[4];
            {
                int rowq = 16*wid + (mi & 1)*8 + r;
                int ch = 2*ks + (mi >> 1);
                ldm4(pa, pB + rowq*128 + ((ch ^ r) << 4));
            }
            uint32_t vr[4][4];
#pragma unroll
            for (int p = 0; p < 4; p++) {
                int krow = 16*ks + (mi & 1)*8 + r;
                int ch = 2*p + (mi >> 1);
                ldm4t(vr[p], vB + krow*128 + ((ch ^ r) << 4));
            }
#pragma unroll
            for (int p = 0; p < 4; p++) {
                mma_f16(o_acc[2*p],   pa, vr[p][0], vr[p][1]);
                mma_f16(o_acc[2*p+1], pa, vr[p][2], vr[p][3]);
            }
        }
    }

    // normalize + write [B,L,D] (tf32-rounded: feeds out-proj A operand)
    float inv0 = 1.0f / l0, inv1 = 1.0f / l1;
    int lr0 = q0 + 16*wid + g, lr1 = lr0 + 8;
#pragma unroll
    for (int nt = 0; nt < 8; nt++) {
        int d = h*HD + nt*8 + 2*c;
        float2 v0 = make_float2(to_tf32(o_acc[nt][0]*inv0), to_tf32(o_acc[nt][1]*inv0));
        float2 v1 = make_float2(to_tf32(o_acc[nt][2]*inv1), to_tf32(o_acc[nt][3]*inv1));
        *(float2*)&out[(size_t)(b*LL + lr0)*DD + d] = v0;
        *(float2*)&out[(size_t)(b*LL + lr1)*DD + d] = v1;
    }
}

// ---------------------------------------------------------------------------
extern "C" void kernel_launch(void* const* d_in, const int* in_sizes, int n_in,
                              void* d_out, int out_size)
{
    const float* x     = (const float*)d_in[0];
    // d_in[1] = pos (32x32 grid, identical per batch — folded into table indexing)
    const float* wn    = (const float*)d_in[2];
    const float* w_in  = (const float*)d_in[3];
    const float* b_in  = (const float*)d_in[4];
    const float* w_out = (const float*)d_in[5];
    const float* b_out = (const float*)d_in[6];
    const float* bp    = (const float*)d_in[7];
    float* out = (float*)d_out;

    float *p_xn, *p_win, *p_wout, *p_att;
    __half *p_q, *p_k, *p_v;
    cudaGetSymbolAddress((void**)&p_xn,   g_xn);
    cudaGetSymbolAddress((void**)&p_win,  g_win);
    cudaGetSymbolAddress((void**)&p_wout, g_wout);
    cudaGetSymbolAddress((void**)&p_q,    g_q);
    cudaGetSymbolAddress((void**)&p_k,    g_k);
    cudaGetSymbolAddress((void**)&p_v,    g_v);
    cudaGetSymbolAddress((void**)&p_att,  g_att);

    bias_tab_kernel<<<HH, 256>>>(bp);
    cvt_tf32_kernel<<<(3*DD*DD + 255)/256, 256>>>(w_in,  p_win,  3*DD*DD);
    cvt_tf32_kernel<<<(DD*DD   + 255)/256, 256>>>(w_out, p_wout, DD*DD);
    rmsnorm_kernel<<<ROWS, 256>>>(x, wn);

    const int gemm_smem = 4 * 128 * SP * 4;   // 81920 B
    cudaFuncSetAttribute(gemm_mma<true>,  cudaFuncAttributeMaxDynamicSharedMemorySize, gemm_smem);
    cudaFuncSetAttribute(gemm_mma<false>, cudaFuncAttributeMaxDynamicSharedMemorySize, gemm_smem);

    gemm_mma<true><<<dim3(2304/128, ROWS/128), 256, gemm_smem>>>(
        p_xn, p_win, b_in, nullptr, p_q, p_k, p_v, 2304);

    const int attn_smem = 49152 + 63*63*4;    // 65028 B
    cudaFuncSetAttribute(attn_h_kernel, cudaFuncAttributeMaxDynamicSharedMemorySize, attn_smem);
    attn_h_kernel<<<dim3(LL/128, BB*HH), 256, attn_smem>>>(p_att);

    gemm_mma<false><<<dim3(DD/128, ROWS/128), 256, gemm_smem>>>(
        p_att, p_wout, b_out, out, nullptr, nullptr, nullptr, DD);
}

// round 8
// speedup vs baseline: 8.0135x; 1.6219x over previous
#include <cuda_runtime.h>
#include <cuda_fp16.h>
#include <math.h>
#include <stdint.h>

// Problem constants
#define BB 8
#define LL 1024
#define DD 768
#define HH 12
#define HD 64
#define ROWS (BB*LL)   // 8192

// Scratch (device globals: allocation-free rule)
__device__ float  g_tab[HH*4096];         // per-head bias table [12][63*63]
__device__ __half g_xnh[ROWS*DD];         // fp16 RMSNorm output
__device__ __half g_winh[3*DD*DD];        // fp16 w_in
__device__ __half g_wouth[DD*DD];         // fp16 w_out
__device__ __half g_q[ROWS*DD];           // [B,H,L,HD], fp16, pre-scaled by 0.125
__device__ __half g_k[ROWS*DD];           // fp16
__device__ __half g_v[ROWS*DD];           // fp16
__device__ __half g_atth[ROWS*DD];        // [B,L,D], fp16 attention output

// ---------------------------------------------------------------------------
// helpers
// ---------------------------------------------------------------------------
__device__ __forceinline__ uint32_t smem_u32(const void* p) {
    uint32_t a;
    asm("{ .reg .u64 t; cvta.to.shared.u64 t, %1; cvt.u32.u64 %0, t; }" : "=r"(a) : "l"(p));
    return a;
}
__device__ __forceinline__ void cpasync16(uint32_t saddr, const void* g) {
    asm volatile("cp.async.cg.shared.global [%0], [%1], 16;" :: "r"(saddr), "l"(g));
}
__device__ __forceinline__ void cp_commit() {
    asm volatile("cp.async.commit_group;" ::: "memory");
}
template<int NN>
__device__ __forceinline__ void cp_wait() {
    asm volatile("cp.async.wait_group %0;" :: "n"(NN) : "memory");
}
__device__ __forceinline__ void mma_f16(float* d, const uint32_t* a, uint32_t b0, uint32_t b1) {
    asm volatile(
        "mma.sync.aligned.m16n8k16.row.col.f32.f16.f16.f32 "
        "{%0,%1,%2,%3}, {%4,%5,%6,%7}, {%8,%9}, {%0,%1,%2,%3};"
        : "+f"(d[0]), "+f"(d[1]), "+f"(d[2]), "+f"(d[3])
        : "r"(a[0]), "r"(a[1]), "r"(a[2]), "r"(a[3]), "r"(b0), "r"(b1));
}
__device__ __forceinline__ void ldm4(uint32_t* f, uint32_t a) {
    asm volatile("ldmatrix.sync.aligned.m8n8.x4.shared.b16 {%0,%1,%2,%3}, [%4];"
                 : "=r"(f[0]), "=r"(f[1]), "=r"(f[2]), "=r"(f[3]) : "r"(a));
}
__device__ __forceinline__ void ldm4t(uint32_t* f, uint32_t a) {
    asm volatile("ldmatrix.sync.aligned.m8n8.x4.trans.shared.b16 {%0,%1,%2,%3}, [%4];"
                 : "=r"(f[0]), "=r"(f[1]), "=r"(f[2]), "=r"(f[3]) : "r"(a));
}

// ---------------------------------------------------------------------------
// 0) float -> half conversion for weights
// ---------------------------------------------------------------------------
__global__ void cvt_h_kernel(const float* __restrict__ src, __half* __restrict__ dst, int n)
{
    int i = blockIdx.x * 256 + threadIdx.x;
    if (i < n) dst[i] = __float2half(src[i]);
}

// ---------------------------------------------------------------------------
// 1) Per-head bias table over (dy,dx) in [-31,31]^2
// ---------------------------------------------------------------------------
__global__ void bias_tab_kernel(const float* __restrict__ bp)
{
    int h = blockIdx.x;
    float o  = bp[h*6+0];
    float c  = bp[h*6+1];
    float w  = bp[h*6+2];
    float p  = bp[h*6+3];
    float dl = bp[h*6+4];
    float m  = bp[h*6+5];
    float ac = fabsf(c);
    float am = fabsf(m);
    float at = fabsf(tanhf(dl));
    for (int i = threadIdx.x; i < 63*63; i += blockDim.x) {
        int dy = i / 63 - 31;
        int dx = i % 63 - 31;
        float fdy = (float)dy, fdx = (float)dx;
        float theta = atan2f(fdx, fdy);
        float r = sqrtf(fdy*fdy + fdx*fdx + 1e-12f);
        float t1 = powf(fmaxf(r - o, 0.0f), ac);
        float co = cosf((theta - p) * w * 0.5f);
        float t2 = 1.0f - at * powf(co*co, am);
        g_tab[h*4096 + i] = t1 * t2;
    }
}

// ---------------------------------------------------------------------------
// 2) RMSNorm: one block per row; emits fp16
// ---------------------------------------------------------------------------
__global__ __launch_bounds__(256) void rmsnorm_kernel(const float* __restrict__ x,
                                                      const float* __restrict__ wn)
{
    int row = blockIdx.x;
    const float* xr = x + (size_t)row * DD;
    float v[3];
    float s = 0.0f;
#pragma unroll
    for (int t = 0; t < 3; t++) {
        v[t] = xr[threadIdx.x + t*256];
        s += v[t]*v[t];
    }
#pragma unroll
    for (int o = 16; o; o >>= 1) s += __shfl_xor_sync(0xffffffffu, s, o);
    __shared__ float ws[8];
    __shared__ float rfac;
    int lane = threadIdx.x & 31, wid = threadIdx.x >> 5;
    if (lane == 0) ws[wid] = s;
    __syncthreads();
    if (threadIdx.x == 0) {
        float t = 0.0f;
#pragma unroll
        for (int i = 0; i < 8; i++) t += ws[i];
        rfac = rsqrtf(t * (1.0f/768.0f) + 1e-5f);
    }
    __syncthreads();
    float f = rfac;
#pragma unroll
    for (int t = 0; t < 3; t++) {
        int j = threadIdx.x + t*256;
        g_xnh[(size_t)row*DD + j] = __float2half(v[t] * f * wn[j]);
    }
}

// ---------------------------------------------------------------------------
// 3/5) fp16 m16n8k16 + ldmatrix NT GEMM: C[M,N] = A[M,768]*Bw[N,768]^T + bias
//      CTA 128x128, BK=64 double-buffered cp.async, 8 warps (2x4), warp 64x32.
//      Smem rows: 64 half = 128B = 8 chunks of 16B, chunk ^= (row&7).
//      SCATTER=true: half2 scatter into q/k/v head-major buffers (q scaled 1/8).
// ---------------------------------------------------------------------------
template<bool SCATTER>
__global__ __launch_bounds__(256) void gemm_h(const __half* __restrict__ A,
                                              const __half* __restrict__ Bw,
                                              const float* __restrict__ bias,
                                              float* __restrict__ Cf,
                                              __half* __restrict__ Qh,
                                              __half* __restrict__ Kh,
                                              __half* __restrict__ Vh,
                                              int N)
{
    extern __shared__ __align__(128) char smc[];
    uint32_t aBase = smem_u32(smc);             // [2][128][64] half, 16KB each
    uint32_t bBase = smem_u32(smc + 32768);     // [2][128][64] half

    int tid = threadIdx.x;
    int wid = tid >> 5, lane = tid & 31;
    int warp_m = wid >> 2, warp_n = wid & 3;    // 2 x 4
    int g = lane >> 2, c = lane & 3;
    int mi = lane >> 3, r = lane & 7;           // ldmatrix lane mapping

    int mBase = blockIdx.y * 128, nBase = blockIdx.x * 128;
    const __half* Agp = A  + (size_t)mBase * DD;
    const __half* Bgp = Bw + (size_t)nBase * DD;

    // staging coords: 1024 chunks per tile, 4 per thread
    int srow[4], sch[4];
    uint32_t soff[4];
#pragma unroll
    for (int t = 0; t < 4; t++) {
        int i = tid + t*256;
        srow[t] = i >> 3;
        sch[t]  = i & 7;
        soff[t] = (uint32_t)(srow[t]*128 + ((sch[t] ^ (srow[t] & 7)) << 4));
    }

    float acc[4][4][4];
#pragma unroll
    for (int mt = 0; mt < 4; mt++)
#pragma unroll
        for (int nt = 0; nt < 4; nt++)
#pragma unroll
            for (int k = 0; k < 4; k++) acc[mt][nt][k] = 0.0f;

    const int NT = DD / 64;   // 12

    // prologue: stage tile 0
#pragma unroll
    for (int t = 0; t < 4; t++) {
        cpasync16(aBase + soff[t], Agp + (size_t)srow[t]*DD + sch[t]*8);
        cpasync16(bBase + soff[t], Bgp + (size_t)srow[t]*DD + sch[t]*8);
    }
    cp_commit();

    for (int kt = 0; kt < NT; kt++) {
        cp_wait<0>();
        __syncthreads();

        if (kt + 1 < NT) {
            int k0 = (kt + 1) * 64;
            uint32_t bo = (uint32_t)(((kt + 1) & 1) * 16384);
#pragma unroll
            for (int t = 0; t < 4; t++) {
                cpasync16(aBase + bo + soff[t], Agp + (size_t)srow[t]*DD + k0 + sch[t]*8);
                cpasync16(bBase + bo + soff[t], Bgp + (size_t)srow[t]*DD + k0 + sch[t]*8);
            }
            cp_commit();
        }

        uint32_t aB = aBase + (kt & 1) * 16384;
        uint32_t bB = bBase + (kt & 1) * 16384;

#pragma unroll
        for (int ks = 0; ks < 4; ks++) {
            int ch = 2*ks + (mi >> 1);
            uint32_t af[4][4];
#pragma unroll
            for (int mt = 0; mt < 4; mt++) {
                int row = warp_m*64 + mt*16 + (mi & 1)*8 + r;
                ldm4(af[mt], aB + row*128 + ((ch ^ r) << 4));
            }
            uint32_t kr[2][4];
#pragma unroll
            for (int p = 0; p < 2; p++) {
                int row = warp_n*32 + p*16 + (mi & 1)*8 + r;
                ldm4(kr[p], bB + row*128 + ((ch ^ r) << 4));
            }
#pragma unroll
            for (int mt = 0; mt < 4; mt++)
#pragma unroll
                for (int p = 0; p < 2; p++) {
                    mma_f16(acc[mt][2*p],   af[mt], kr[p][0], kr[p][2]);
                    mma_f16(acc[mt][2*p+1], af[mt], kr[p][1], kr[p][3]);
                }
        }
        __syncthreads();
    }

    // epilogue
#pragma unroll
    for (int mt = 0; mt < 4; mt++) {
        int r0 = mBase + warp_m*64 + mt*16 + g;
#pragma unroll
        for (int nt = 0; nt < 4; nt++) {
            int gc = nBase + warp_n*32 + nt*8 + 2*c;
            float bz0 = bias[gc], bz1 = bias[gc+1];
            if (SCATTER) {
                int which = gc / 768;
                int rem = gc - which * 768;
                int h = rem >> 6, hd = rem & 63;
                float sc = (which == 0) ? 0.125f : 1.0f;   // fold 1/sqrt(64) into Q
                __half* dst = (which == 0) ? Qh : (which == 1 ? Kh : Vh);
                __half2 v0 = __floats2half2_rn((acc[mt][nt][0] + bz0)*sc, (acc[mt][nt][1] + bz1)*sc);
                __half2 v1 = __floats2half2_rn((acc[mt][nt][2] + bz0)*sc, (acc[mt][nt][3] + bz1)*sc);
                int b0 = r0 >> 10, l0 = r0 & 1023;
                *(__half2*)&dst[(size_t)((b0*HH + h)*LL + l0)*HD + hd] = v0;
                int r1 = r0 + 8;
                int b1 = r1 >> 10, l1 = r1 & 1023;
                *(__half2*)&dst[(size_t)((b1*HH + h)*LL + l1)*HD + hd] = v1;
            } else {
                float2 v0 = make_float2(acc[mt][nt][0] + bz0, acc[mt][nt][1] + bz1);
                float2 v1 = make_float2(acc[mt][nt][2] + bz0, acc[mt][nt][3] + bz1);
                *(float2*)&Cf[(size_t)r0 * N + gc] = v0;
                *(float2*)&Cf[(size_t)(r0 + 8) * N + gc] = v1;
            }
        }
    }
}

// ---------------------------------------------------------------------------
// 4) Flash attention, fp16 m16n8k16 + ldmatrix (unchanged math; half output).
// ---------------------------------------------------------------------------
__global__ __launch_bounds__(256) void attn_h_kernel(__half* __restrict__ out)
{
    extern __shared__ __align__(128) char smc[];
    char*  Pbase = smc + 32768;
    float* tabs  = (float*)(smc + 49152);

    int tid = threadIdx.x;
    int wid = tid >> 5, lane = tid & 31;
    int g = lane >> 2, c = lane & 3;
    int mi = lane >> 3, r = lane & 7;
    int qt = blockIdx.x, bh = blockIdx.y;
    int b = bh / HH, h = bh - b * HH;
    int q0 = qt * 128;

    const __half* qg = g_q + ((size_t)bh * LL + q0) * HD;
    const __half* kg = g_k + (size_t)bh * LL * HD;
    const __half* vg = g_v + (size_t)bh * LL * HD;

    uint32_t kBase = smem_u32(smc);
    uint32_t vBase = smem_u32(smc + 16384);
    uint32_t pB    = smem_u32(Pbase);

    // Stage Q (128x64 half) into P area, swizzled  [group 0]
#pragma unroll
    for (int it = 0; it < 4; it++) {
        int i = tid + it*256;
        int row = i >> 3, ch = i & 7;
        cpasync16(pB + row*128 + ((ch ^ (row & 7)) << 4), qg + row*64 + ch*8);
    }
    cp_commit();
    // Prefetch K/V tile 0  [group 1]
#pragma unroll
    for (int it = 0; it < 2; it++) {
        int i = tid + it*256;
        int row = i >> 3, ch = i & 7;
        uint32_t so = row*128 + ((ch ^ (row & 7)) << 4);
        cpasync16(kBase + so, kg + row*64 + ch*8);
        cpasync16(vBase + so, vg + row*64 + ch*8);
    }
    cp_commit();
    for (int i = tid; i < 63*63; i += 256) tabs[i] = g_tab[h*4096 + i];

    cp_wait<1>();
    __syncthreads();

    uint32_t qf[4][4];
    {
        int rowq = 16*wid + (mi & 1)*8 + r;
#pragma unroll
        for (int ks = 0; ks < 4; ks++) {
            int ch = 2*ks + (mi >> 1);
            ldm4(qf[ks], pB + rowq*128 + ((ch ^ r) << 4));
        }
    }

    int qr0 = q0 + 16*wid + g, qr1 = qr0 + 8;
    const float* ptA = tabs + ((qr0 >> 5) + 31)*63 + (qr0 & 31) + 31 - 2*c;
    const float* ptB = tabs + ((qr1 >> 5) + 31)*63 + (qr1 & 31) + 31 - 2*c;

    float m0 = -1e30f, m1 = -1e30f, l0 = 0.0f, l1 = 0.0f;
    float o_acc[8][4];
#pragma unroll
    for (int nt = 0; nt < 8; nt++)
#pragma unroll
        for (int k = 0; k < 4; k++) o_acc[nt][k] = 0.0f;

    for (int t = 0; t < 16; t++) {
        uint32_t kB = kBase + (t & 1)*8192;
        uint32_t vB = vBase + (t & 1)*8192;
        cp_wait<0>();
        __syncthreads();

        if (t + 1 < 16) {
            int kr0 = (t + 1) * 64;
            uint32_t kBn = kBase + ((t + 1) & 1)*8192;
            uint32_t vBn = vBase + ((t + 1) & 1)*8192;
#pragma unroll
            for (int it = 0; it < 2; it++) {
                int i = tid + it*256;
                int row = i >> 3, ch = i & 7;
                uint32_t so = row*128 + ((ch ^ (row & 7)) << 4);
                cpasync16(kBn + so, kg + (size_t)(kr0 + row)*64 + ch*8);
                cpasync16(vBn + so, vg + (size_t)(kr0 + row)*64 + ch*8);
            }
            cp_commit();
        }

        // ---- S = Q K^T ----
        float s[8][4];
#pragma unroll
        for (int nt = 0; nt < 8; nt++)
#pragma unroll
            for (int k = 0; k < 4; k++) s[nt][k] = 0.0f;

#pragma unroll
        for (int ks = 0; ks < 4; ks++) {
            uint32_t kr[4][4];
#pragma unroll
            for (int p = 0; p < 4; p++) {
                int keyrow = 16*p + (mi & 1)*8 + r;
                int ch = 2*ks + (mi >> 1);
                ldm4(kr[p], kB + keyrow*128 + ((ch ^ r) << 4));
            }
#pragma unroll
            for (int p = 0; p < 4; p++) {
                mma_f16(s[2*p],   qf[ks], kr[p][0], kr[p][2]);
                mma_f16(s[2*p+1], qf[ks], kr[p][1], kr[p][3]);
            }
        }

        // ---- bias + online softmax ----
        float mx0 = -1e30f, mx1 = -1e30f;
#pragma unroll
        for (int nt = 0; nt < 8; nt++) {
            const int off = (nt < 4) ? (-8*nt) : (32 - 8*nt - 63);
            s[nt][0] += ptA[off];
            s[nt][1] += ptA[off - 1];
            s[nt][2] += ptB[off];
            s[nt][3] += ptB[off - 1];
            mx0 = fmaxf(mx0, fmaxf(s[nt][0], s[nt][1]));
            mx1 = fmaxf(mx1, fmaxf(s[nt][2], s[nt][3]));
        }
        ptA -= 126; ptB -= 126;
        mx0 = fmaxf(mx0, __shfl_xor_sync(0xffffffffu, mx0, 1));
        mx0 = fmaxf(mx0, __shfl_xor_sync(0xffffffffu, mx0, 2));
        mx1 = fmaxf(mx1, __shfl_xor_sync(0xffffffffu, mx1, 1));
        mx1 = fmaxf(mx1, __shfl_xor_sync(0xffffffffu, mx1, 2));

        float mn0 = fmaxf(m0, mx0), mn1 = fmaxf(m1, mx1);
        float sc0 = __expf(m0 - mn0), sc1 = __expf(m1 - mn1);
        float rs0 = 0.0f, rs1 = 0.0f;
#pragma unroll
        for (int nt = 0; nt < 8; nt++) {
            s[nt][0] = __expf(s[nt][0] - mn0);
            s[nt][1] = __expf(s[nt][1] - mn0);
            s[nt][2] = __expf(s[nt][2] - mn1);
            s[nt][3] = __expf(s[nt][3] - mn1);
            rs0 += s[nt][0] + s[nt][1];
            rs1 += s[nt][2] + s[nt][3];
        }
        rs0 += __shfl_xor_sync(0xffffffffu, rs0, 1);
        rs0 += __shfl_xor_sync(0xffffffffu, rs0, 2);
        rs1 += __shfl_xor_sync(0xffffffffu, rs1, 1);
        rs1 += __shfl_xor_sync(0xffffffffu, rs1, 2);
        l0 = l0*sc0 + rs0; m0 = mn0;
        l1 = l1*sc1 + rs1; m1 = mn1;

        int rowp0 = 16*wid + g;
#pragma unroll
        for (int nt = 0; nt < 8; nt++) {
            o_acc[nt][0] *= sc0; o_acc[nt][1] *= sc0;
            o_acc[nt][2] *= sc1; o_acc[nt][3] *= sc1;
            uint32_t soff = ((nt ^ g) << 4) + 4*c;
            *(__half2*)(Pbase + rowp0*128 + soff)       = __floats2half2_rn(s[nt][0], s[nt][1]);
            *(__half2*)(Pbase + (rowp0 + 8)*128 + soff) = __floats2half2_rn(s[nt][2], s[nt][3]);
        }

        // ---- O += P V ----
#pragma unroll
        for (int ks = 0; ks < 4; ks++) {
            uint32_t pa[4];
            {
                int rowq = 16*wid + (mi & 1)*8 + r;
                int ch = 2*ks + (mi >> 1);
                ldm4(pa, pB + rowq*128 + ((ch ^ r) << 4));
            }
            uint32_t vr[4][4];
#pragma unroll
            for (int p = 0; p < 4; p++) {
                int krow = 16*ks + (mi & 1)*8 + r;
                int ch = 2*p + (mi >> 1);
                ldm4t(vr[p], vB + krow*128 + ((ch ^ r) << 4));
            }
#pragma unroll
            for (int p = 0; p < 4; p++) {
                mma_f16(o_acc[2*p],   pa, vr[p][0], vr[p][1]);
                mma_f16(o_acc[2*p+1], pa, vr[p][2], vr[p][3]);
            }
        }
    }

    // normalize + write [B,L,D] fp16 (feeds out-proj A operand)
    float inv0 = 1.0f / l0, inv1 = 1.0f / l1;
    int lr0 = q0 + 16*wid + g, lr1 = lr0 + 8;
#pragma unroll
    for (int nt = 0; nt < 8; nt++) {
        int d = h*HD + nt*8 + 2*c;
        *(__half2*)&out[(size_t)(b*LL + lr0)*DD + d] =
            __floats2half2_rn(o_acc[nt][0]*inv0, o_acc[nt][1]*inv0);
        *(__half2*)&out[(size_t)(b*LL + lr1)*DD + d] =
            __floats2half2_rn(o_acc[nt][2]*inv1, o_acc[nt][3]*inv1);
    }
}

// ---------------------------------------------------------------------------
extern "C" void kernel_launch(void* const* d_in, const int* in_sizes, int n_in,
                              void* d_out, int out_size)
{
    const float* x     = (const float*)d_in[0];
    // d_in[1] = pos (32x32 grid, identical per batch — folded into table indexing)
    const float* wn    = (const float*)d_in[2];
    const float* w_in  = (const float*)d_in[3];
    const float* b_in  = (const float*)d_in[4];
    const float* w_out = (const float*)d_in[5];
    const float* b_out = (const float*)d_in[6];
    const float* bp    = (const float*)d_in[7];
    float* out = (float*)d_out;

    __half *p_xnh, *p_winh, *p_wouth, *p_q, *p_k, *p_v, *p_atth;
    cudaGetSymbolAddress((void**)&p_xnh,   g_xnh);
    cudaGetSymbolAddress((void**)&p_winh,  g_winh);
    cudaGetSymbolAddress((void**)&p_wouth, g_wouth);
    cudaGetSymbolAddress((void**)&p_q,     g_q);
    cudaGetSymbolAddress((void**)&p_k,     g_k);
    cudaGetSymbolAddress((void**)&p_v,     g_v);
    cudaGetSymbolAddress((void**)&p_atth,  g_atth);

    bias_tab_kernel<<<HH, 256>>>(bp);
    cvt_h_kernel<<<(3*DD*DD + 255)/256, 256>>>(w_in,  p_winh,  3*DD*DD);
    cvt_h_kernel<<<(DD*DD   + 255)/256, 256>>>(w_out, p_wouth, DD*DD);
    rmsnorm_kernel<<<ROWS, 256>>>(x, wn);

    const int gemm_smem = 65536;
    cudaFuncSetAttribute(gemm_h<true>,  cudaFuncAttributeMaxDynamicSharedMemorySize, gemm_smem);
    cudaFuncSetAttribute(gemm_h<false>, cudaFuncAttributeMaxDynamicSharedMemorySize, gemm_smem);

    gemm_h<true><<<dim3(2304/128, ROWS/128), 256, gemm_smem>>>(
        p_xnh, p_winh, b_in, nullptr, p_q, p_k, p_v, 2304);

    const int attn_smem = 49152 + 63*63*4;    // 65028 B
    cudaFuncSetAttribute(attn_h_kernel, cudaFuncAttributeMaxDynamicSharedMemorySize, attn_smem);
    attn_h_kernel<<<dim3(LL/128, BB*HH), 256, attn_smem>>>(p_atth);

    gemm_h<false><<<dim3(DD/128, ROWS/128), 256, gemm_smem>>>(
        p_atth, p_wouth, b_out, out, nullptr, nullptr, nullptr, DD);
}

// round 9
// speedup vs baseline: 8.2506x; 1.0296x over previous
#include <cuda_runtime.h>
#include <cuda_fp16.h>
#include <math.h>
#include <stdint.h>

// Problem constants
#define BB 8
#define LL 1024
#define DD 768
#define HH 12
#define HD 64
#define ROWS (BB*LL)   // 8192

// Scratch (device globals: allocation-free rule)
__device__ float  g_tab[HH*4096];         // per-head bias table [12][63*63]
__device__ __half g_xnh[ROWS*DD];         // fp16 RMSNorm output
__device__ __half g_winh[3*DD*DD];        // fp16 w_in
__device__ __half g_wouth[DD*DD];         // fp16 w_out
__device__ __half g_q[ROWS*DD];           // [B,H,L,HD], fp16, pre-scaled by 0.125
__device__ __half g_k[ROWS*DD];           // fp16
__device__ __half g_v[ROWS*DD];           // fp16
__device__ __half g_atth[ROWS*DD];        // [B,L,D], fp16 attention output

// ---------------------------------------------------------------------------
// helpers
// ---------------------------------------------------------------------------
__device__ __forceinline__ uint32_t smem_u32(const void* p) {
    uint32_t a;
    asm("{ .reg .u64 t; cvta.to.shared.u64 t, %1; cvt.u32.u64 %0, t; }" : "=r"(a) : "l"(p));
    return a;
}
__device__ __forceinline__ void cpasync16(uint32_t saddr, const void* g) {
    asm volatile("cp.async.cg.shared.global [%0], [%1], 16;" :: "r"(saddr), "l"(g));
}
__device__ __forceinline__ void cp_commit() {
    asm volatile("cp.async.commit_group;" ::: "memory");
}
template<int NN>
__device__ __forceinline__ void cp_wait() {
    asm volatile("cp.async.wait_group %0;" :: "n"(NN) : "memory");
}
__device__ __forceinline__ void mma_f16(float* d, const uint32_t* a, uint32_t b0, uint32_t b1) {
    asm volatile(
        "mma.sync.aligned.m16n8k16.row.col.f32.f16.f16.f32 "
        "{%0,%1,%2,%3}, {%4,%5,%6,%7}, {%8,%9}, {%0,%1,%2,%3};"
        : "+f"(d[0]), "+f"(d[1]), "+f"(d[2]), "+f"(d[3])
        : "r"(a[0]), "r"(a[1]), "r"(a[2]), "r"(a[3]), "r"(b0), "r"(b1));
}
__device__ __forceinline__ void ldm4(uint32_t* f, uint32_t a) {
    asm volatile("ldmatrix.sync.aligned.m8n8.x4.shared.b16 {%0,%1,%2,%3}, [%4];"
                 : "=r"(f[0]), "=r"(f[1]), "=r"(f[2]), "=r"(f[3]) : "r"(a));
}
__device__ __forceinline__ void ldm4t(uint32_t* f, uint32_t a) {
    asm volatile("ldmatrix.sync.aligned.m8n8.x4.trans.shared.b16 {%0,%1,%2,%3}, [%4];"
                 : "=r"(f[0]), "=r"(f[1]), "=r"(f[2]), "=r"(f[3]) : "r"(a));
}

// ---------------------------------------------------------------------------
// 1) Fused prep: blocks 0..11 -> per-head bias table; rest -> weight f32->f16
// ---------------------------------------------------------------------------
#define WCONV4 ((3*DD*DD + DD*DD) / 4)          // 589824 float4-quads
#define PREP_BLKS (HH + WCONV4/256)             // 12 + 2304

__global__ __launch_bounds__(256) void prep_kernel(const float* __restrict__ bp,
                                                   const float* __restrict__ w_in,
                                                   const float* __restrict__ w_out)
{
    int blk = blockIdx.x;
    if (blk < HH) {
        int h = blk;
        float o  = bp[h*6+0];
        float c  = bp[h*6+1];
        float w  = bp[h*6+2];
        float p  = bp[h*6+3];
        float dl = bp[h*6+4];
        float m  = bp[h*6+5];
        float ac = fabsf(c);
        float am = fabsf(m);
        float at = fabsf(tanhf(dl));
        for (int i = threadIdx.x; i < 63*63; i += 256) {
            int dy = i / 63 - 31;
            int dx = i % 63 - 31;
            float fdy = (float)dy, fdx = (float)dx;
            float theta = atan2f(fdx, fdy);
            float r = sqrtf(fdy*fdy + fdx*fdx + 1e-12f);
            float t1 = powf(fmaxf(r - o, 0.0f), ac);
            float co = cosf((theta - p) * w * 0.5f);
            float t2 = 1.0f - at * powf(co*co, am);
            g_tab[h*4096 + i] = t1 * t2;
        }
    } else {
        int q = (blk - HH) * 256 + threadIdx.x;   // quad index
        int i = q * 4;
        const int n1 = 3*DD*DD;
        float4 v;
        __half* dst;
        if (i < n1) {
            v = *(const float4*)(w_in + i);
            dst = g_winh + i;
        } else {
            v = *(const float4*)(w_out + (i - n1));
            dst = g_wouth + (i - n1);
        }
        ((__half2*)dst)[0] = __floats2half2_rn(v.x, v.y);
        ((__half2*)dst)[1] = __floats2half2_rn(v.z, v.w);
    }
}

// ---------------------------------------------------------------------------
// 2) RMSNorm: one block (192 threads) per row; float4 in, half4 out
// ---------------------------------------------------------------------------
__global__ __launch_bounds__(192) void rmsnorm_kernel(const float* __restrict__ x,
                                                      const float* __restrict__ wn)
{
    int row = blockIdx.x;
    int tid = threadIdx.x;
    float4 v = *(const float4*)(x + (size_t)row * DD + tid*4);
    float s = v.x*v.x + v.y*v.y + v.z*v.z + v.w*v.w;
#pragma unroll
    for (int o = 16; o; o >>= 1) s += __shfl_xor_sync(0xffffffffu, s, o);
    __shared__ float ws[6];
    __shared__ float rfac;
    int lane = tid & 31, wid = tid >> 5;
    if (lane == 0) ws[wid] = s;
    __syncthreads();
    if (tid == 0) {
        float t = ws[0] + ws[1] + ws[2] + ws[3] + ws[4] + ws[5];
        rfac = rsqrtf(t * (1.0f/768.0f) + 1e-5f);
    }
    __syncthreads();
    float f = rfac;
    float4 w4 = *(const float4*)(wn + tid*4);
    __half* dst = g_xnh + (size_t)row * DD + tid*4;
    ((__half2*)dst)[0] = __floats2half2_rn(v.x*f*w4.x, v.y*f*w4.y);
    ((__half2*)dst)[1] = __floats2half2_rn(v.z*f*w4.z, v.w*f*w4.w);
}

// ---------------------------------------------------------------------------
// 3/5) fp16 m16n8k16 + ldmatrix NT GEMM: C[M,N] = A[M,768]*Bw[N,768]^T + bias
//      CTA 128x128, BK=64 double-buffered cp.async, 8 warps (2x4), warp 64x32.
//      Smem rows: 64 half = 128B = 8 chunks of 16B, chunk ^= (row&7).
//      SCATTER=true: half2 scatter into q/k/v head-major buffers (q scaled 1/8).
// ---------------------------------------------------------------------------
template<bool SCATTER>
__global__ __launch_bounds__(256) void gemm_h(const __half* __restrict__ A,
                                              const __half* __restrict__ Bw,
                                              const float* __restrict__ bias,
                                              float* __restrict__ Cf,
                                              __half* __restrict__ Qh,
                                              __half* __restrict__ Kh,
                                              __half* __restrict__ Vh,
                                              int N)
{
    extern __shared__ __align__(128) char smc[];
    uint32_t aBase = smem_u32(smc);             // [2][128][64] half, 16KB each
    uint32_t bBase = smem_u32(smc + 32768);     // [2][128][64] half

    int tid = threadIdx.x;
    int wid = tid >> 5, lane = tid & 31;
    int warp_m = wid >> 2, warp_n = wid & 3;    // 2 x 4
    int g = lane >> 2, c = lane & 3;
    int mi = lane >> 3, r = lane & 7;           // ldmatrix lane mapping

    int mBase = blockIdx.y * 128, nBase = blockIdx.x * 128;
    const __half* Agp = A  + (size_t)mBase * DD;
    const __half* Bgp = Bw + (size_t)nBase * DD;

    // staging coords: 1024 chunks per tile, 4 per thread
    int srow[4], sch[4];
    uint32_t soff[4];
#pragma unroll
    for (int t = 0; t < 4; t++) {
        int i = tid + t*256;
        srow[t] = i >> 3;
        sch[t]  = i & 7;
        soff[t] = (uint32_t)(srow[t]*128 + ((sch[t] ^ (srow[t] & 7)) << 4));
    }

    float acc[4][4][4];
#pragma unroll
    for (int mt = 0; mt < 4; mt++)
#pragma unroll
        for (int nt = 0; nt < 4; nt++)
#pragma unroll
            for (int k = 0; k < 4; k++) acc[mt][nt][k] = 0.0f;

    const int NT = DD / 64;   // 12

    // prologue: stage tile 0
#pragma unroll
    for (int t = 0; t < 4; t++) {
        cpasync16(aBase + soff[t], Agp + (size_t)srow[t]*DD + sch[t]*8);
        cpasync16(bBase + soff[t], Bgp + (size_t)srow[t]*DD + sch[t]*8);
    }
    cp_commit();

    for (int kt = 0; kt < NT; kt++) {
        cp_wait<0>();
        __syncthreads();

        if (kt + 1 < NT) {
            int k0 = (kt + 1) * 64;
            uint32_t bo = (uint32_t)(((kt + 1) & 1) * 16384);
#pragma unroll
            for (int t = 0; t < 4; t++) {
                cpasync16(aBase + bo + soff[t], Agp + (size_t)srow[t]*DD + k0 + sch[t]*8);
                cpasync16(bBase + bo + soff[t], Bgp + (size_t)srow[t]*DD + k0 + sch[t]*8);
            }
            cp_commit();
        }

        uint32_t aB = aBase + (kt & 1) * 16384;
        uint32_t bB = bBase + (kt & 1) * 16384;

#pragma unroll
        for (int ks = 0; ks < 4; ks++) {
            int ch = 2*ks + (mi >> 1);
            uint32_t af[4][4];
#pragma unroll
            for (int mt = 0; mt < 4; mt++) {
                int row = warp_m*64 + mt*16 + (mi & 1)*8 + r;
                ldm4(af[mt], aB + row*128 + ((ch ^ r) << 4));
            }
            uint32_t kr[2][4];
#pragma unroll
            for (int p = 0; p < 2; p++) {
                int row = warp_n*32 + p*16 + (mi & 1)*8 + r;
                ldm4(kr[p], bB + row*128 + ((ch ^ r) << 4));
            }
#pragma unroll
            for (int mt = 0; mt < 4; mt++)
#pragma unroll
                for (int p = 0; p < 2; p++) {
                    mma_f16(acc[mt][2*p],   af[mt], kr[p][0], kr[p][2]);
                    mma_f16(acc[mt][2*p+1], af[mt], kr[p][1], kr[p][3]);
                }
        }
        __syncthreads();
    }

    // epilogue
#pragma unroll
    for (int mt = 0; mt < 4; mt++) {
        int r0 = mBase + warp_m*64 + mt*16 + g;
#pragma unroll
        for (int nt = 0; nt < 4; nt++) {
            int gc = nBase + warp_n*32 + nt*8 + 2*c;
            float bz0 = bias[gc], bz1 = bias[gc+1];
            if (SCATTER) {
                int which = gc / 768;
                int rem = gc - which * 768;
                int h = rem >> 6, hd = rem & 63;
                float sc = (which == 0) ? 0.125f : 1.0f;   // fold 1/sqrt(64) into Q
                __half* dst = (which == 0) ? Qh : (which == 1 ? Kh : Vh);
                __half2 v0 = __floats2half2_rn((acc[mt][nt][0] + bz0)*sc, (acc[mt][nt][1] + bz1)*sc);
                __half2 v1 = __floats2half2_rn((acc[mt][nt][2] + bz0)*sc, (acc[mt][nt][3] + bz1)*sc);
                int b0 = r0 >> 10, l0 = r0 & 1023;
                *(__half2*)&dst[(size_t)((b0*HH + h)*LL + l0)*HD + hd] = v0;
                int r1 = r0 + 8;
                int b1 = r1 >> 10, l1 = r1 & 1023;
                *(__half2*)&dst[(size_t)((b1*HH + h)*LL + l1)*HD + hd] = v1;
            } else {
                float2 v0 = make_float2(acc[mt][nt][0] + bz0, acc[mt][nt][1] + bz1);
                float2 v1 = make_float2(acc[mt][nt][2] + bz0, acc[mt][nt][3] + bz1);
                *(float2*)&Cf[(size_t)r0 * N + gc] = v0;
                *(float2*)&Cf[(size_t)(r0 + 8) * N + gc] = v1;
            }
        }
    }
}

// ---------------------------------------------------------------------------
// 4) Flash attention, fp16 m16n8k16 + ldmatrix (half output).
// ---------------------------------------------------------------------------
__global__ __launch_bounds__(256) void attn_h_kernel(__half* __restrict__ out)
{
    extern __shared__ __align__(128) char smc[];
    char*  Pbase = smc + 32768;
    float* tabs  = (float*)(smc + 49152);

    int tid = threadIdx.x;
    int wid = tid >> 5, lane = tid & 31;
    int g = lane >> 2, c = lane & 3;
    int mi = lane >> 3, r = lane & 7;
    int qt = blockIdx.x, bh = blockIdx.y;
    int b = bh / HH, h = bh - b * HH;
    int q0 = qt * 128;

    const __half* qg = g_q + ((size_t)bh * LL + q0) * HD;
    const __half* kg = g_k + (size_t)bh * LL * HD;
    const __half* vg = g_v + (size_t)bh * LL * HD;

    uint32_t kBase = smem_u32(smc);
    uint32_t vBase = smem_u32(smc + 16384);
    uint32_t pB    = smem_u32(Pbase);

    // Stage Q (128x64 half) into P area, swizzled  [group 0]
#pragma unroll
    for (int it = 0; it < 4; it++) {
        int i = tid + it*256;
        int row = i >> 3, ch = i & 7;
        cpasync16(pB + row*128 + ((ch ^ (row & 7)) << 4), qg + row*64 + ch*8);
    }
    cp_commit();
    // Prefetch K/V tile 0  [group 1]
#pragma unroll
    for (int it = 0; it < 2; it++) {
        int i = tid + it*256;
        int row = i >> 3, ch = i & 7;
        uint32_t so = row*128 + ((ch ^ (row & 7)) << 4);
        cpasync16(kBase + so, kg + row*64 + ch*8);
        cpasync16(vBase + so, vg + row*64 + ch*8);
    }
    cp_commit();
    for (int i = tid; i < 63*63; i += 256) tabs[i] = g_tab[h*4096 + i];

    cp_wait<1>();
    __syncthreads();

    uint32_t qf[4][4];
    {
        int rowq = 16*wid + (mi & 1)*8 + r;
#pragma unroll
        for (int ks = 0; ks < 4; ks++) {
            int ch = 2*ks + (mi >> 1);
            ldm4(qf[ks], pB + rowq*128 + ((ch ^ r) << 4));
        }
    }

    int qr0 = q0 + 16*wid + g, qr1 = qr0 + 8;
    const float* ptA = tabs + ((qr0 >> 5) + 31)*63 + (qr0 & 31) + 31 - 2*c;
    const float* ptB = tabs + ((qr1 >> 5) + 31)*63 + (qr1 & 31) + 31 - 2*c;

    float m0 = -1e30f, m1 = -1e30f, l0 = 0.0f, l1 = 0.0f;
    float o_acc[8][4];
#pragma unroll
    for (int nt = 0; nt < 8; nt++)
#pragma unroll
        for (int k = 0; k < 4; k++) o_acc[nt][k] = 0.0f;

    for (int t = 0; t < 16; t++) {
        uint32_t kB = kBase + (t & 1)*8192;
        uint32_t vB = vBase + (t & 1)*8192;
        cp_wait<0>();
        __syncthreads();

        if (t + 1 < 16) {
            int kr0 = (t + 1) * 64;
            uint32_t kBn = kBase + ((t + 1) & 1)*8192;
            uint32_t vBn = vBase + ((t + 1) & 1)*8192;
#pragma unroll
            for (int it = 0; it < 2; it++) {
                int i = tid + it*256;
                int row = i >> 3, ch = i & 7;
                uint32_t so = row*128 + ((ch ^ (row & 7)) << 4);
                cpasync16(kBn + so, kg + (size_t)(kr0 + row)*64 + ch*8);
                cpasync16(vBn + so, vg + (size_t)(kr0 + row)*64 + ch*8);
            }
            cp_commit();
        }

        // ---- S = Q K^T ----
        float s[8][4];
#pragma unroll
        for (int nt = 0; nt < 8; nt++)
#pragma unroll
            for (int k = 0; k < 4; k++) s[nt][k] = 0.0f;

#pragma unroll
        for (int ks = 0; ks < 4; ks++) {
            uint32_t kr[4][4];
#pragma unroll
            for (int p = 0; p < 4; p++) {
                int keyrow = 16*p + (mi & 1)*8 + r;
                int ch = 2*ks + (mi >> 1);
                ldm4(kr[p], kB + keyrow*128 + ((ch ^ r) << 4));
            }
#pragma unroll
            for (int p = 0; p < 4; p++) {
                mma_f16(s[2*p],   qf[ks], kr[p][0], kr[p][2]);
                mma_f16(s[2*p+1], qf[ks], kr[p][1], kr[p][3]);
            }
        }

        // ---- bias + online softmax ----
        float mx0 = -1e30f, mx1 = -1e30f;
#pragma unroll
        for (int nt = 0; nt < 8; nt++) {
            const int off = (nt < 4) ? (-8*nt) : (32 - 8*nt - 63);
            s[nt][0] += ptA[off];
            s[nt][1] += ptA[off - 1];
            s[nt][2] += ptB[off];
            s[nt][3] += ptB[off - 1];
            mx0 = fmaxf(mx0, fmaxf(s[nt][0], s[nt][1]));
            mx1 = fmaxf(mx1, fmaxf(s[nt][2], s[nt][3]));
        }
        ptA -= 126; ptB -= 126;
        mx0 = fmaxf(mx0, __shfl_xor_sync(0xffffffffu, mx0, 1));
        mx0 = fmaxf(mx0, __shfl_xor_sync(0xffffffffu, mx0, 2));
        mx1 = fmaxf(mx1, __shfl_xor_sync(0xffffffffu, mx1, 1));
        mx1 = fmaxf(mx1, __shfl_xor_sync(0xffffffffu, mx1, 2));

        float mn0 = fmaxf(m0, mx0), mn1 = fmaxf(m1, mx1);
        float sc0 = __expf(m0 - mn0), sc1 = __expf(m1 - mn1);
        float rs0 = 0.0f, rs1 = 0.0f;
#pragma unroll
        for (int nt = 0; nt < 8; nt++) {
            s[nt][0] = __expf(s[nt][0] - mn0);
            s[nt][1] = __expf(s[nt][1] - mn0);
            s[nt][2] = __expf(s[nt][2] - mn1);
            s[nt][3] = __expf(s[nt][3] - mn1);
            rs0 += s[nt][0] + s[nt][1];
            rs1 += s[nt][2] + s[nt][3];
        }
        rs0 += __shfl_xor_sync(0xffffffffu, rs0, 1);
        rs0 += __shfl_xor_sync(0xffffffffu, rs0, 2);
        rs1 += __shfl_xor_sync(0xffffffffu, rs1, 1);
        rs1 += __shfl_xor_sync(0xffffffffu, rs1, 2);
        l0 = l0*sc0 + rs0; m0 = mn0;
        l1 = l1*sc1 + rs1; m1 = mn1;

        int rowp0 = 16*wid + g;
#pragma unroll
        for (int nt = 0; nt < 8; nt++) {
            o_acc[nt][0] *= sc0; o_acc[nt][1] *= sc0;
            o_acc[nt][2] *= sc1; o_acc[nt][3] *= sc1;
            uint32_t soff = ((nt ^ g) << 4) + 4*c;
            *(__half2*)(Pbase + rowp0*128 + soff)       = __floats2half2_rn(s[nt][0], s[nt][1]);
            *(__half2*)(Pbase + (rowp0 + 8)*128 + soff) = __floats2half2_rn(s[nt][2], s[nt][3]);
        }

        // ---- O += P V ----
#pragma unroll
        for (int ks = 0; ks < 4; ks++) {
            uint32_t pa[4];
            {
                int rowq = 16*wid + (mi & 1)*8 + r;
                int ch = 2*ks + (mi >> 1);
                ldm4(pa, pB + rowq*128 + ((ch ^ r) << 4));
            }
            uint32_t vr[4][4];
#pragma unroll
            for (int p = 0; p < 4; p++) {
                int krow = 16*ks + (mi & 1)*8 + r;
                int ch = 2*p + (mi >> 1);
                ldm4t(vr[p], vB + krow*128 + ((ch ^ r) << 4));
            }
#pragma unroll
            for (int p = 0; p < 4; p++) {
                mma_f16(o_acc[2*p],   pa, vr[p][0], vr[p][1]);
                mma_f16(o_acc[2*p+1], pa, vr[p][2], vr[p][3]);
            }
        }
    }

    // normalize + write [B,L,D] fp16 (feeds out-proj A operand)
    float inv0 = 1.0f / l0, inv1 = 1.0f / l1;
    int lr0 = q0 + 16*wid + g, lr1 = lr0 + 8;
#pragma unroll
    for (int nt = 0; nt < 8; nt++) {
        int d = h*HD + nt*8 + 2*c;
        *(__half2*)&out[(size_t)(b*LL + lr0)*DD + d] =
            __floats2half2_rn(o_acc[nt][0]*inv0, o_acc[nt][1]*inv0);
        *(__half2*)&out[(size_t)(b*LL + lr1)*DD + d] =
            __floats2half2_rn(o_acc[nt][2]*inv1, o_acc[nt][3]*inv1);
    }
}

// ---------------------------------------------------------------------------
extern "C" void kernel_launch(void* const* d_in, const int* in_sizes, int n_in,
                              void* d_out, int out_size)
{
    const float* x     = (const float*)d_in[0];
    // d_in[1] = pos (32x32 grid, identical per batch — folded into table indexing)
    const float* wn    = (const float*)d_in[2];
    const float* w_in  = (const float*)d_in[3];
    const float* b_in  = (const float*)d_in[4];
    const float* w_out = (const float*)d_in[5];
    const float* b_out = (const float*)d_in[6];
    const float* bp    = (const float*)d_in[7];
    float* out = (float*)d_out;

    __half *p_xnh, *p_winh, *p_wouth, *p_q, *p_k, *p_v, *p_atth;
    cudaGetSymbolAddress((void**)&p_xnh,   g_xnh);
    cudaGetSymbolAddress((void**)&p_winh,  g_winh);
    cudaGetSymbolAddress((void**)&p_wouth, g_wouth);
    cudaGetSymbolAddress((void**)&p_q,     g_q);
    cudaGetSymbolAddress((void**)&p_k,     g_k);
    cudaGetSymbolAddress((void**)&p_v,     g_v);
    cudaGetSymbolAddress((void**)&p_atth,  g_atth);

    prep_kernel<<<PREP_BLKS, 256>>>(bp, w_in, w_out);
    rmsnorm_kernel<<<ROWS, 192>>>(x, wn);

    const int gemm_smem = 65536;
    cudaFuncSetAttribute(gemm_h<true>,  cudaFuncAttributeMaxDynamicSharedMemorySize, gemm_smem);
    cudaFuncSetAttribute(gemm_h<false>, cudaFuncAttributeMaxDynamicSharedMemorySize, gemm_smem);

    gemm_h<true><<<dim3(2304/128, ROWS/128), 256, gemm_smem>>>(
        p_xnh, p_winh, b_in, nullptr, p_q, p_k, p_v, 2304);

    const int attn_smem = 49152 + 63*63*4;    // 65028 B
    cudaFuncSetAttribute(attn_h_kernel, cudaFuncAttributeMaxDynamicSharedMemorySize, attn_smem);
    attn_h_kernel<<<dim3(LL/128, BB*HH), 256, attn_smem>>>(p_atth);

    gemm_h<false><<<dim3(DD/128, ROWS/128), 256, gemm_smem>>>(
        p_atth, p_wouth, b_out, out, nullptr, nullptr, nullptr, DD);
}